// round 11
// baseline (speedup 1.0000x reference)
#include <cuda_runtime.h>
#include <cuda_fp16.h>
#include <cstdint>

static constexpr int B_  = 8;
static constexpr int N_  = 16384;
static constexpr int S_  = 2048;
static constexpr int C1_ = 128;
static constexpr int C2_ = 256;
static constexpr int K1_ = 384;
static constexpr int O_  = 256;
static constexpr float BN_EPS  = 1e-5f;
static constexpr float CNT_INV = 1.0f / (float)(B_ * N_);

// ---------------- device-global scratch (no cudaMalloc allowed) ---------------
__device__ __half g_xq[(size_t)B_ * N_ * K1_];   // concat input, fp16 [n][k]
__device__ __half g_y [(size_t)B_ * N_ * O_];    // y1 then y2, fp16 (n-major)
__device__ float  g_p2t[(size_t)B_ * S_ * C2_];  // points2 transposed [B][S][C]
__device__ int    g_idx[(size_t)B_ * N_ * 3];
__device__ float  g_w  [(size_t)B_ * N_ * 3];
__device__ __half g_w0q[O_ * K1_];               // W0 fp16
__device__ __half g_w1q[O_ * O_];                // W1 fp16
__device__ float  g_psum[256 * 1024], g_pssq[256 * 1024];
__device__ float  g_sb1[512], g_sb2[512];

// ---------------- small PTX helpers ------------------------------------------
__device__ __forceinline__ uint32_t smem_u32(const void* p) {
    uint32_t a;
    asm("{ .reg .u64 t; cvta.to.shared.u64 t, %1; cvt.u32.u64 %0, t; }"
        : "=r"(a) : "l"(p));
    return a;
}
__device__ __forceinline__ void cpa16(uint32_t dst, const void* src) {
    asm volatile("cp.async.cg.shared.global [%0], [%1], 16;"
                 :: "r"(dst), "l"(src) : "memory");
}
#define CP_COMMIT() asm volatile("cp.async.commit_group;" ::: "memory")
#define CP_WAIT0()  asm volatile("cp.async.wait_group 0;" ::: "memory")
#define CP_WAIT1()  asm volatile("cp.async.wait_group 1;" ::: "memory")

__device__ __forceinline__ void ldsm4(uint32_t addr, uint32_t* r) {
    asm volatile("ldmatrix.sync.aligned.m8n8.x4.shared.b16 {%0,%1,%2,%3}, [%4];"
                 : "=r"(r[0]), "=r"(r[1]), "=r"(r[2]), "=r"(r[3]) : "r"(addr));
}
__device__ __forceinline__ void mma16816(float* c, const uint32_t* a, const uint32_t* b) {
    asm volatile(
        "mma.sync.aligned.m16n8k16.row.col.f32.f16.f16.f32 "
        "{%0,%1,%2,%3}, {%4,%5,%6,%7}, {%8,%9}, {%0,%1,%2,%3};"
        : "+f"(c[0]), "+f"(c[1]), "+f"(c[2]), "+f"(c[3])
        : "r"(a[0]), "r"(a[1]), "r"(a[2]), "r"(a[3]), "r"(b[0]), "r"(b[1]));
}

// ---------------- kNN (4 queries per thread, exact squared distances) ---------
__global__ __launch_bounds__(256) void knn_kernel(
    const float* __restrict__ xyz1, const float* __restrict__ xyz2)
{
    __shared__ float4 sp[S_];
    const int b = blockIdx.y;
    const int t = threadIdx.x;
    for (int s = t; s < S_; s += 256) {
        const float* p = xyz2 + ((size_t)b * S_ + s) * 3;
        sp[s] = make_float4(p[0], p[1], p[2], 0.0f);
    }
    __syncthreads();

    const int nb = blockIdx.x * 1024 + t;
    float qx[4], qy[4], qz[4];
    float d0[4], d1[4], d2[4];
    int   i0[4], i1[4], i2[4];
    #pragma unroll
    for (int j = 0; j < 4; j++) {
        const float* q = xyz1 + ((size_t)b * N_ + nb + j * 256) * 3;
        qx[j] = q[0]; qy[j] = q[1]; qz[j] = q[2];
        d0[j] = 3.4e38f; d1[j] = 3.4e38f; d2[j] = 3.4e38f;
        i0[j] = 0; i1[j] = 0; i2[j] = 0;
    }
    #pragma unroll 2
    for (int s = 0; s < S_; s++) {
        float4 p = sp[s];
        #pragma unroll
        for (int j = 0; j < 4; j++) {
            float dx = qx[j] - p.x, dy = qy[j] - p.y, dz = qz[j] - p.z;
            float d = fmaf(dz, dz, fmaf(dy, dy, dx * dx));
            if (d < d2[j]) {
                if (d < d1[j]) {
                    d2[j] = d1[j]; i2[j] = i1[j];
                    if (d < d0[j]) { d1[j] = d0[j]; i1[j] = i0[j]; d0[j] = d; i0[j] = s; }
                    else           { d1[j] = d;  i1[j] = s; }
                } else { d2[j] = d; i2[j] = s; }
            }
        }
    }
    #pragma unroll
    for (int j = 0; j < 4; j++) {
        float a = fmaxf(d0[j], 1e-10f), bb = fmaxf(d1[j], 1e-10f), c = fmaxf(d2[j], 1e-10f);
        float w0 = 1.0f / a, w1 = 1.0f / bb, w2 = 1.0f / c;
        float sw = w0 + w1 + w2;
        size_t base = ((size_t)b * N_ + nb + j * 256) * 3;
        g_idx[base] = i0[j]; g_idx[base + 1] = i1[j]; g_idx[base + 2] = i2[j];
        g_w[base] = w0 / sw; g_w[base + 1] = w1 / sw; g_w[base + 2] = w2 / sw;
    }
}

// ---------------- transpose points2 [B][C][S] -> [B][S][C] --------------------
__global__ void transpose_p2_kernel(const float* __restrict__ p2)
{
    __shared__ float tile[32][33];
    const int b  = blockIdx.z;
    const int s0 = blockIdx.x * 32;
    const int c0 = blockIdx.y * 32;
    #pragma unroll
    for (int r = 0; r < 4; r++) {
        int c = c0 + threadIdx.y + r * 8;
        tile[threadIdx.y + r * 8][threadIdx.x] =
            p2[((size_t)b * C2_ + c) * S_ + s0 + threadIdx.x];
    }
    __syncthreads();
    #pragma unroll
    for (int r = 0; r < 4; r++) {
        int s = s0 + threadIdx.y + r * 8;
        g_p2t[((size_t)b * S_ + s) * C2_ + c0 + threadIdx.x] =
            tile[threadIdx.x][threadIdx.y + r * 8];
    }
}

// ---------------- gather + weighted sum -> xcat channels [0,256) --------------
__global__ __launch_bounds__(256) void gather_kernel()
{
    const int b  = blockIdx.y;
    const int n0 = blockIdx.x * 32;
    const int t  = threadIdx.x;          // channel
    #pragma unroll 2
    for (int nl = 0; nl < 32; nl++) {
        size_t base = ((size_t)b * N_ + n0 + nl) * 3;
        int i0 = g_idx[base], i1 = g_idx[base + 1], i2 = g_idx[base + 2];
        float w0 = g_w[base], w1 = g_w[base + 1], w2 = g_w[base + 2];
        const float* r0 = g_p2t + ((size_t)b * S_ + i0) * C2_;
        const float* r1 = g_p2t + ((size_t)b * S_ + i1) * C2_;
        const float* r2 = g_p2t + ((size_t)b * S_ + i2) * C2_;
        float v = fmaf(w2, r2[t], fmaf(w1, r1[t], w0 * r0[t]));
        g_xq[((size_t)b * N_ + n0 + nl) * K1_ + t] = __float2half_rn(v);
    }
}

// ---------------- points1 transpose -> xcat channels [256,384) ----------------
__global__ void p1t_kernel(const float* __restrict__ p1)
{
    __shared__ float tile[32][33];
    const int b  = blockIdx.z;
    const int n0 = blockIdx.x * 32;
    const int c0 = blockIdx.y * 32;
    #pragma unroll
    for (int r = 0; r < 4; r++) {
        int c = c0 + threadIdx.y + r * 8;
        tile[threadIdx.y + r * 8][threadIdx.x] =
            p1[((size_t)b * C1_ + c) * N_ + n0 + threadIdx.x];
    }
    __syncthreads();
    #pragma unroll
    for (int r = 0; r < 4; r++) {
        int n = n0 + threadIdx.y + r * 8;
        float v = tile[threadIdx.x][threadIdx.y + r * 8];
        g_xq[((size_t)b * N_ + n) * K1_ + 256 + c0 + threadIdx.x] = __float2half_rn(v);
    }
}

// ---------------- weight fp16 convert -----------------------------------------
__global__ void wconv_kernel(const float* __restrict__ w,
                             __half* __restrict__ q, int n)
{
    int i = blockIdx.x * 256 + threadIdx.x;
    if (i < n) q[i] = __float2half_rn(w[i]);
}

// ---------------- mma.sync fp16 GEMM (3-stage pipeline) -----------------------
// FUSE=0: D = W @ X             (layer 1; X = g_xq)
// FUSE=1: D = W @ relu(sc*X+bs) (layer 2; X = raw y1; affine in fp32 on B frags)
// CTA: 256 thr = 8 warps (4 in M x 2 in N). Warp tile 64x64.
// Epilogue: BN partials from fp32 accs; y stored fp16 via smem-staged flush.
template<int KDIM, bool FUSE>
__global__ __launch_bounds__(256) void gemm_mma(
    const __half* __restrict__ Aq, const __half* __restrict__ Bq,
    const float* __restrict__ bias, __half* __restrict__ Y,
    float* __restrict__ psum, float* __restrict__ pssq,
    const float* __restrict__ sbn)
{
    constexpr int NS = KDIM / 32;                 // K stages of 32
    constexpr uint32_t PITCH  = 80;               // 64B data + 16B pad
    constexpr uint32_t OFF_B  = 256u * PITCH;     // 20480
    constexpr uint32_t STAGE  = OFF_B + 128u * PITCH;  // 30720

    extern __shared__ char sdyn[];
    __shared__ float sm_s[2][256], sm_q[2][256];
    __shared__ float2 sscf[128], sbbf[128];       // fp32 per-channel-pair scale/bias

    const int tid  = threadIdx.x;
    const int lane = tid & 31, wid = tid >> 5;
    const int mw   = wid & 3;        // M block of 64
    const int nw   = wid >> 2;       // N block of 64
    const int b    = blockIdx.y;
    const int n0   = blockIdx.x * 128;
    const size_t bn0 = (size_t)b * N_ + n0;
    const uint32_t sb0 = smem_u32(sdyn);

    if (FUSE && tid < 128) {
        sscf[tid] = make_float2(sbn[2 * tid], sbn[2 * tid + 1]);
        sbbf[tid] = make_float2(sbn[256 + 2 * tid], sbn[256 + 2 * tid + 1]);
    }

    auto load_stage = [&](int kt, int buf) {
        uint32_t base = sb0 + (uint32_t)buf * STAGE;
        #pragma unroll
        for (int i = 0; i < 4; i++) {              // A: 256 rows x 4 chunks
            int c = tid + i * 256;
            int row = (c >> 2) & 255, ch = c & 3;
            const __half* src = Aq + (size_t)row * KDIM + kt + ch * 8;
            cpa16(base + (uint32_t)row * PITCH + ch * 16, src);
        }
        #pragma unroll
        for (int i = 0; i < 2; i++) {              // B: 128 rows x 4 chunks
            int c = tid + i * 256;
            int row = (c >> 2) & 127, ch = c & 3;
            const __half* src = Bq + (bn0 + row) * KDIM + kt + ch * 8;
            cpa16(base + OFF_B + (uint32_t)row * PITCH + ch * 16, src);
        }
        CP_COMMIT();
    };

    float acc[4][8][4] = {};

    load_stage(0, 0);
    load_stage(32, 1);

    #pragma unroll 1
    for (int s = 0; s < NS; s++) {
        CP_WAIT1();                // stage s resident (s+1 may remain in flight)
        __syncthreads();           // visibility + all warps done with buf (s+2)%3
        if (s + 2 < NS) load_stage((s + 2) * 32, (s + 2) % 3);

        uint32_t base = sb0 + (uint32_t)(s % 3) * STAGE;
        #pragma unroll
        for (int ks = 0; ks < 2; ks++) {
            uint32_t a[4][4];
            #pragma unroll
            for (int mt = 0; mt < 4; mt++) {
                uint32_t row = (uint32_t)(mw * 64 + mt * 16 + (lane & 15));
                ldsm4(base + row * PITCH + ks * 32 + ((lane >> 4) << 4), a[mt]);
            }
            // fp32 per-k scale/bias for this thread's B fragment positions
            float2 scA, scB, bsA, bsB;
            if (FUSE) {
                int kp = s * 16 + ks * 8 + (lane & 3);
                scA = sscf[kp];     bsA = sbbf[kp];
                scB = sscf[kp + 4]; bsB = sbbf[kp + 4];
            }
            #pragma unroll
            for (int ntp = 0; ntp < 4; ntp++) {
                uint32_t rowB = (uint32_t)(nw * 64 + ntp * 16
                               + ((lane >> 4) << 3) + (lane & 7));
                uint32_t bfr[4];
                ldsm4(base + OFF_B + rowB * PITCH
                      + ks * 32 + (((lane >> 3) & 1) << 4), bfr);
                if (FUSE) {
                    #pragma unroll
                    for (int j = 0; j < 4; j++) {
                        const float2 sc = (j & 1) ? scB : scA;
                        const float2 bs = (j & 1) ? bsB : bsA;
                        float2 v = __half22float2(*(__half2*)&bfr[j]);
                        v.x = fmaxf(fmaf(v.x, sc.x, bs.x), 0.0f);
                        v.y = fmaxf(fmaf(v.y, sc.y, bs.y), 0.0f);
                        *(__half2*)&bfr[j] = __floats2half2_rn(v.x, v.y);
                    }
                }
                #pragma unroll
                for (int h = 0; h < 2; h++) {
                    int nt = ntp * 2 + h;
                    #pragma unroll
                    for (int mt = 0; mt < 4; mt++)
                        mma16816(acc[mt][nt], a[mt], &bfr[h * 2]);
                }
            }
        }
    }
    __syncthreads();               // all compute done before sy reuses stage smem

    // ---- epilogue: bias, BN partials, smem-staged fp16 coalesced flush -------
    float* sy = (float*)sdyn;             // [64][260] per N-half
    const int r = lane >> 2;
    float csum[8] = {}, cssq[8] = {};

    #pragma unroll
    for (int half = 0; half < 2; half++) {
        if (nw == half) {
            #pragma unroll
            for (int mt = 0; mt < 4; mt++) {
                const int m0 = mw * 64 + mt * 16 + r;
                const int m1 = m0 + 8;
                const float bv0 = bias[m0], bv1 = bias[m1];
                #pragma unroll
                for (int nt = 0; nt < 8; nt++) {
                    float* c = acc[mt][nt];
                    int nl = nt * 8 + (lane & 3) * 2;
                    float v0 = c[0] + bv0, v1 = c[1] + bv0;
                    float v2 = c[2] + bv1, v3 = c[3] + bv1;
                    sy[nl * 260 + m0]       = v0;
                    sy[(nl + 1) * 260 + m0] = v1;
                    sy[nl * 260 + m1]       = v2;
                    sy[(nl + 1) * 260 + m1] = v3;
                    csum[mt * 2]     += v0 + v1;
                    cssq[mt * 2]     += fmaf(v0, v0, v1 * v1);
                    csum[mt * 2 + 1] += v2 + v3;
                    cssq[mt * 2 + 1] += fmaf(v2, v2, v3 * v3);
                }
            }
        }
        __syncthreads();
        // coalesced fp16 flush: 64 rows x 512B, two rows per iteration
        #pragma unroll 8
        for (int i = 0; i < 32; i++) {
            int row = i * 2 + (tid >> 7);
            int c2  = tid & 127;
            __half2 hp = __floats2half2_rn(sy[row * 260 + c2 * 2],
                                           sy[row * 260 + c2 * 2 + 1]);
            *(__half2*)(Y + (bn0 + half * 64 + row) * 256 + c2 * 2) = hp;
        }
        __syncthreads();
    }

    // BN partials
    #pragma unroll
    for (int j = 0; j < 8; j++) {
        csum[j] += __shfl_xor_sync(0xffffffffu, csum[j], 1);
        csum[j] += __shfl_xor_sync(0xffffffffu, csum[j], 2);
        cssq[j] += __shfl_xor_sync(0xffffffffu, cssq[j], 1);
        cssq[j] += __shfl_xor_sync(0xffffffffu, cssq[j], 2);
    }
    if ((lane & 3) == 0) {
        #pragma unroll
        for (int mt = 0; mt < 4; mt++) {
            #pragma unroll
            for (int h = 0; h < 2; h++) {
                int ch = mw * 64 + mt * 16 + r + h * 8;
                sm_s[nw][ch] = csum[mt * 2 + h];
                sm_q[nw][ch] = cssq[mt * 2 + h];
            }
        }
    }
    __syncthreads();
    {
        int cta = blockIdx.x + blockIdx.y * gridDim.x;
        psum[tid * 1024 + cta] = sm_s[0][tid] + sm_s[1][tid];
        pssq[tid * 1024 + cta] = sm_q[0][tid] + sm_q[1][tid];
    }
}

// ---------------- BN fold: reduce 1024 partials per channel -------------------
__global__ __launch_bounds__(256) void stats2_kernel(
    const float* __restrict__ g, const float* __restrict__ beta,
    float* __restrict__ sb)
{
    const int o = blockIdx.x;
    const int t = threadIdx.x;
    float s = 0.0f, ss = 0.0f;
    #pragma unroll
    for (int i = 0; i < 4; i++) {
        s  += g_psum[o * 1024 + t * 4 + i];
        ss += g_pssq[o * 1024 + t * 4 + i];
    }
    const int lane = t & 31, w = t >> 5;
    #pragma unroll
    for (int off = 16; off; off >>= 1) {
        s  += __shfl_down_sync(0xffffffffu, s,  off);
        ss += __shfl_down_sync(0xffffffffu, ss, off);
    }
    __shared__ float rs[8], rss[8];
    if (lane == 0) { rs[w] = s; rss[w] = ss; }
    __syncthreads();
    if (t == 0) {
        float ts = 0.0f, tss = 0.0f;
        #pragma unroll
        for (int i = 0; i < 8; i++) { ts += rs[i]; tss += rss[i]; }
        float mean = ts * CNT_INV;
        float var  = tss * CNT_INV - mean * mean;
        float rstd = rsqrtf(var + BN_EPS);
        float sc = g[o] * rstd;
        sb[o]       = sc;
        sb[256 + o] = beta[o] - mean * sc;
    }
}

// ---------------- final norm + relu + transpose -> out [B][256][N] ------------
__global__ __launch_bounds__(256) void outt_kernel(
    const __half* __restrict__ y, const float* __restrict__ sb,
    float* __restrict__ out)
{
    __shared__ float tile[32][33];
    const int b  = blockIdx.z;
    const int n0 = blockIdx.x * 32;
    const int m0 = blockIdx.y * 32;
    const float sc = sb[m0 + threadIdx.x];
    const float bs = sb[256 + m0 + threadIdx.x];
    #pragma unroll
    for (int r = 0; r < 4; r++) {
        int n = n0 + threadIdx.y + r * 8;
        float v = __half2float(y[((size_t)b * N_ + n) * 256 + m0 + threadIdx.x]);
        tile[threadIdx.y + r * 8][threadIdx.x] = fmaxf(fmaf(v, sc, bs), 0.0f);
    }
    __syncthreads();
    #pragma unroll
    for (int r = 0; r < 4; r++) {
        int m = m0 + threadIdx.y + r * 8;
        out[((size_t)b * 256 + m) * N_ + n0 + threadIdx.x] =
            tile[threadIdx.x][threadIdx.y + r * 8];
    }
}

// ---------------- launcher ----------------------------------------------------
extern "C" void kernel_launch(void* const* d_in, const int* in_sizes, int n_in,
                              void* d_out, int out_size)
{
    const float* xyz1 = (const float*)d_in[0];
    const float* xyz2 = (const float*)d_in[1];
    const float* pts1 = (const float*)d_in[2];
    const float* pts2 = (const float*)d_in[3];
    const float* W0   = (const float*)d_in[4];
    const float* b0   = (const float*)d_in[5];
    const float* gg0  = (const float*)d_in[6];
    const float* be0  = (const float*)d_in[7];
    const float* W1   = (const float*)d_in[8];
    const float* b1   = (const float*)d_in[9];
    const float* gg1  = (const float*)d_in[10];
    const float* be1  = (const float*)d_in[11];
    float* out = (float*)d_out;

    __half *xq, *w0q, *w1q, *y;
    float *psum, *pssq, *sb1, *sb2;
    cudaGetSymbolAddress((void**)&xq,  g_xq);
    cudaGetSymbolAddress((void**)&w0q, g_w0q);
    cudaGetSymbolAddress((void**)&w1q, g_w1q);
    cudaGetSymbolAddress((void**)&y,   g_y);
    cudaGetSymbolAddress((void**)&psum, g_psum);
    cudaGetSymbolAddress((void**)&pssq, g_pssq);
    cudaGetSymbolAddress((void**)&sb1, g_sb1);
    cudaGetSymbolAddress((void**)&sb2, g_sb2);

    const int GEMM_SMEM = 3 * 30720;   // 3-stage ring (92160 B; sy tile 66560 fits)
    cudaFuncSetAttribute(gemm_mma<K1_, false>, cudaFuncAttributeMaxDynamicSharedMemorySize, GEMM_SMEM);
    cudaFuncSetAttribute(gemm_mma<O_,  true >, cudaFuncAttributeMaxDynamicSharedMemorySize, GEMM_SMEM);

    // prep
    wconv_kernel<<<(O_ * K1_ + 255) / 256, 256>>>(W0, w0q, O_ * K1_);
    wconv_kernel<<<(O_ * O_  + 255) / 256, 256>>>(W1, w1q, O_ * O_);
    knn_kernel<<<dim3(N_ / 1024, B_), 256>>>(xyz1, xyz2);
    transpose_p2_kernel<<<dim3(S_ / 32, C2_ / 32, B_), dim3(32, 8)>>>(pts2);
    gather_kernel<<<dim3(N_ / 32, B_), 256>>>();
    p1t_kernel<<<dim3(N_ / 32, C1_ / 32, B_), dim3(32, 8)>>>(pts1);

    // layer 1 -> y1
    gemm_mma<K1_, false><<<dim3(N_ / 128, B_), 256, GEMM_SMEM>>>(
        w0q, xq, b0, y, psum, pssq, nullptr);
    stats2_kernel<<<256, 256>>>(gg0, be0, sb1);

    // layer 2: reads raw y1, fp32 norm+relu on B fragments, writes y2 in place
    gemm_mma<O_, true><<<dim3(N_ / 128, B_), 256, GEMM_SMEM>>>(
        w1q, y, b1, y, psum, pssq, sb1);
    stats2_kernel<<<256, 256>>>(gg1, be1, sb2);

    // output
    outt_kernel<<<dim3(N_ / 32, 8, B_), dim3(32, 8)>>>(y, sb2, out);
}

// round 12
// speedup vs baseline: 1.1782x; 1.1782x over previous
#include <cuda_runtime.h>
#include <cuda_fp16.h>
#include <cstdint>

static constexpr int B_  = 8;
static constexpr int N_  = 16384;
static constexpr int S_  = 2048;
static constexpr int C1_ = 128;
static constexpr int C2_ = 256;
static constexpr int K1_ = 384;
static constexpr int O_  = 256;
static constexpr float BN_EPS  = 1e-5f;
static constexpr float CNT_INV = 1.0f / (float)(B_ * N_);

// ---------------- device-global scratch (no cudaMalloc allowed) ---------------
__device__ __half g_xq[(size_t)B_ * N_ * K1_];   // concat input, fp16 [n][k]
__device__ __half g_y [(size_t)B_ * N_ * O_];    // y1 then y2, fp16 (n-major)
__device__ float  g_p2t[(size_t)B_ * S_ * C2_];  // points2 transposed [B][S][C]
__device__ int    g_idx[(size_t)B_ * N_ * 3];
__device__ float  g_w  [(size_t)B_ * N_ * 3];
__device__ __half g_w0q[O_ * K1_];               // W0 fp16
__device__ __half g_w1q[O_ * O_];                // W1 fp16
__device__ float  g_psum[256 * 1024], g_pssq[256 * 1024];
__device__ float  g_sb1[512], g_sb2[512];

// ---------------- small PTX helpers ------------------------------------------
__device__ __forceinline__ uint32_t smem_u32(const void* p) {
    uint32_t a;
    asm("{ .reg .u64 t; cvta.to.shared.u64 t, %1; cvt.u32.u64 %0, t; }"
        : "=r"(a) : "l"(p));
    return a;
}
__device__ __forceinline__ void cpa16(uint32_t dst, const void* src) {
    asm volatile("cp.async.cg.shared.global [%0], [%1], 16;"
                 :: "r"(dst), "l"(src) : "memory");
}
#define CP_COMMIT() asm volatile("cp.async.commit_group;" ::: "memory")
#define CP_WAIT0()  asm volatile("cp.async.wait_group 0;" ::: "memory")
#define CP_WAIT1()  asm volatile("cp.async.wait_group 1;" ::: "memory")

__device__ __forceinline__ void ldsm4(uint32_t addr, uint32_t* r) {
    asm volatile("ldmatrix.sync.aligned.m8n8.x4.shared.b16 {%0,%1,%2,%3}, [%4];"
                 : "=r"(r[0]), "=r"(r[1]), "=r"(r[2]), "=r"(r[3]) : "r"(addr));
}
__device__ __forceinline__ void mma16816(float* c, const uint32_t* a, const uint32_t* b) {
    asm volatile(
        "mma.sync.aligned.m16n8k16.row.col.f32.f16.f16.f32 "
        "{%0,%1,%2,%3}, {%4,%5,%6,%7}, {%8,%9}, {%0,%1,%2,%3};"
        : "+f"(c[0]), "+f"(c[1]), "+f"(c[2]), "+f"(c[3])
        : "r"(a[0]), "r"(a[1]), "r"(a[2]), "r"(a[3]), "r"(b[0]), "r"(b[1]));
}

// ---------------- kNN (8 queries per thread, exact squared distances) ---------
__global__ __launch_bounds__(256) void knn_kernel(
    const float* __restrict__ xyz1, const float* __restrict__ xyz2)
{
    __shared__ float4 sp[S_];
    const int b = blockIdx.y;
    const int t = threadIdx.x;
    for (int s = t; s < S_; s += 256) {
        const float* p = xyz2 + ((size_t)b * S_ + s) * 3;
        sp[s] = make_float4(p[0], p[1], p[2], 0.0f);
    }
    __syncthreads();

    const int nb = blockIdx.x * 2048 + t;
    float qx[8], qy[8], qz[8];
    float d0[8], d1[8], d2[8];
    int   i0[8], i1[8], i2[8];
    #pragma unroll
    for (int j = 0; j < 8; j++) {
        const float* q = xyz1 + ((size_t)b * N_ + nb + j * 256) * 3;
        qx[j] = q[0]; qy[j] = q[1]; qz[j] = q[2];
        d0[j] = 3.4e38f; d1[j] = 3.4e38f; d2[j] = 3.4e38f;
        i0[j] = 0; i1[j] = 0; i2[j] = 0;
    }
    #pragma unroll 2
    for (int s = 0; s < S_; s++) {
        float4 p = sp[s];
        #pragma unroll
        for (int j = 0; j < 8; j++) {
            float dx = qx[j] - p.x, dy = qy[j] - p.y, dz = qz[j] - p.z;
            float d = fmaf(dz, dz, fmaf(dy, dy, dx * dx));
            if (d < d2[j]) {
                if (d < d1[j]) {
                    d2[j] = d1[j]; i2[j] = i1[j];
                    if (d < d0[j]) { d1[j] = d0[j]; i1[j] = i0[j]; d0[j] = d; i0[j] = s; }
                    else           { d1[j] = d;  i1[j] = s; }
                } else { d2[j] = d; i2[j] = s; }
            }
        }
    }
    #pragma unroll
    for (int j = 0; j < 8; j++) {
        float a = fmaxf(d0[j], 1e-10f), bb = fmaxf(d1[j], 1e-10f), c = fmaxf(d2[j], 1e-10f);
        float w0 = 1.0f / a, w1 = 1.0f / bb, w2 = 1.0f / c;
        float sw = w0 + w1 + w2;
        size_t base = ((size_t)b * N_ + nb + j * 256) * 3;
        g_idx[base] = i0[j]; g_idx[base + 1] = i1[j]; g_idx[base + 2] = i2[j];
        g_w[base] = w0 / sw; g_w[base + 1] = w1 / sw; g_w[base + 2] = w2 / sw;
    }
}

// ---------------- transpose points2 [B][C][S] -> [B][S][C] --------------------
__global__ void transpose_p2_kernel(const float* __restrict__ p2)
{
    __shared__ float tile[32][33];
    const int b  = blockIdx.z;
    const int s0 = blockIdx.x * 32;
    const int c0 = blockIdx.y * 32;
    #pragma unroll
    for (int r = 0; r < 4; r++) {
        int c = c0 + threadIdx.y + r * 8;
        tile[threadIdx.y + r * 8][threadIdx.x] =
            p2[((size_t)b * C2_ + c) * S_ + s0 + threadIdx.x];
    }
    __syncthreads();
    #pragma unroll
    for (int r = 0; r < 4; r++) {
        int s = s0 + threadIdx.y + r * 8;
        g_p2t[((size_t)b * S_ + s) * C2_ + c0 + threadIdx.x] =
            tile[threadIdx.x][threadIdx.y + r * 8];
    }
}

// ---------------- gather + weighted sum -> xcat channels [0,256) --------------
__global__ __launch_bounds__(256) void gather_kernel()
{
    const int b  = blockIdx.y;
    const int n0 = blockIdx.x * 32;
    const int t  = threadIdx.x;          // channel
    #pragma unroll 2
    for (int nl = 0; nl < 32; nl++) {
        size_t base = ((size_t)b * N_ + n0 + nl) * 3;
        int i0 = g_idx[base], i1 = g_idx[base + 1], i2 = g_idx[base + 2];
        float w0 = g_w[base], w1 = g_w[base + 1], w2 = g_w[base + 2];
        const float* r0 = g_p2t + ((size_t)b * S_ + i0) * C2_;
        const float* r1 = g_p2t + ((size_t)b * S_ + i1) * C2_;
        const float* r2 = g_p2t + ((size_t)b * S_ + i2) * C2_;
        float v = fmaf(w2, r2[t], fmaf(w1, r1[t], w0 * r0[t]));
        g_xq[((size_t)b * N_ + n0 + nl) * K1_ + t] = __float2half_rn(v);
    }
}

// ---------------- points1 transpose -> xcat channels [256,384) ----------------
__global__ void p1t_kernel(const float* __restrict__ p1)
{
    __shared__ float tile[32][33];
    const int b  = blockIdx.z;
    const int n0 = blockIdx.x * 32;
    const int c0 = blockIdx.y * 32;
    #pragma unroll
    for (int r = 0; r < 4; r++) {
        int c = c0 + threadIdx.y + r * 8;
        tile[threadIdx.y + r * 8][threadIdx.x] =
            p1[((size_t)b * C1_ + c) * N_ + n0 + threadIdx.x];
    }
    __syncthreads();
    #pragma unroll
    for (int r = 0; r < 4; r++) {
        int n = n0 + threadIdx.y + r * 8;
        float v = tile[threadIdx.x][threadIdx.y + r * 8];
        g_xq[((size_t)b * N_ + n) * K1_ + 256 + c0 + threadIdx.x] = __float2half_rn(v);
    }
}

// ---------------- weight fp16 convert -----------------------------------------
__global__ void wconv_kernel(const float* __restrict__ w,
                             __half* __restrict__ q, int n)
{
    int i = blockIdx.x * 256 + threadIdx.x;
    if (i < n) q[i] = __float2half_rn(w[i]);
}

// ---------------- mma.sync fp16 GEMM (R10 2-stage structure) ------------------
// FUSE=0: D = W @ X             (layer 1; X = g_xq)
// FUSE=1: D = W @ relu(sc*X+bs) (layer 2; X = raw y1; affine in fp32 on B frags)
// CTA: 256 thr = 8 warps (4 in M x 2 in N). Warp tile 64x64.
// Epilogue: BN partials from fp32 accs; y stored fp16 via smem-staged flush.
template<int KDIM, bool FUSE>
__global__ __launch_bounds__(256) void gemm_mma(
    const __half* __restrict__ Aq, const __half* __restrict__ Bq,
    const float* __restrict__ bias, __half* __restrict__ Y,
    float* __restrict__ psum, float* __restrict__ pssq,
    const float* __restrict__ sbn)
{
    constexpr int NS = KDIM / 32;                 // K stages of 32
    constexpr uint32_t PITCH  = 80;               // 64B data + 16B pad
    constexpr uint32_t OFF_B  = 256u * PITCH;     // 20480
    constexpr uint32_t STAGE  = OFF_B + 128u * PITCH;  // 30720

    extern __shared__ char sdyn[];
    __shared__ float sm_s[2][256], sm_q[2][256];
    __shared__ float2 sscf[128], sbbf[128];       // fp32 per-channel-pair scale/bias

    const int tid  = threadIdx.x;
    const int lane = tid & 31, wid = tid >> 5;
    const int mw   = wid & 3;        // M block of 64
    const int nw   = wid >> 2;       // N block of 64
    const int b    = blockIdx.y;
    const int n0   = blockIdx.x * 128;
    const size_t bn0 = (size_t)b * N_ + n0;
    const uint32_t sb0 = smem_u32(sdyn);

    if (FUSE && tid < 128) {
        sscf[tid] = make_float2(sbn[2 * tid], sbn[2 * tid + 1]);
        sbbf[tid] = make_float2(sbn[256 + 2 * tid], sbn[256 + 2 * tid + 1]);
    }

    auto load_stage = [&](int kt, int buf) {
        uint32_t base = sb0 + (uint32_t)buf * STAGE;
        #pragma unroll
        for (int i = 0; i < 4; i++) {              // A: 256 rows x 4 chunks
            int c = tid + i * 256;
            int row = (c >> 2) & 255, ch = c & 3;
            const __half* src = Aq + (size_t)row * KDIM + kt + ch * 8;
            cpa16(base + (uint32_t)row * PITCH + ch * 16, src);
        }
        #pragma unroll
        for (int i = 0; i < 2; i++) {              // B: 128 rows x 4 chunks
            int c = tid + i * 256;
            int row = (c >> 2) & 127, ch = c & 3;
            const __half* src = Bq + (bn0 + row) * KDIM + kt + ch * 8;
            cpa16(base + OFF_B + (uint32_t)row * PITCH + ch * 16, src);
        }
        CP_COMMIT();
    };

    float acc[4][8][4] = {};

    load_stage(0, 0);

    #pragma unroll 1
    for (int s = 0; s < NS; s++) {
        if (s + 1 < NS) { load_stage((s + 1) * 32, (s + 1) & 1); CP_WAIT1(); }
        else            { CP_WAIT0(); }
        __syncthreads();

        uint32_t base = sb0 + (uint32_t)(s & 1) * STAGE;
        #pragma unroll
        for (int ks = 0; ks < 2; ks++) {
            uint32_t a[4][4];
            #pragma unroll
            for (int mt = 0; mt < 4; mt++) {
                uint32_t row = (uint32_t)(mw * 64 + mt * 16 + (lane & 15));
                ldsm4(base + row * PITCH + ks * 32 + ((lane >> 4) << 4), a[mt]);
            }
            // fp32 per-k scale/bias for this thread's B fragment positions
            float2 scA, scB, bsA, bsB;
            if (FUSE) {
                int kp = s * 16 + ks * 8 + (lane & 3);
                scA = sscf[kp];     bsA = sbbf[kp];
                scB = sscf[kp + 4]; bsB = sbbf[kp + 4];
            }
            #pragma unroll
            for (int ntp = 0; ntp < 4; ntp++) {
                uint32_t rowB = (uint32_t)(nw * 64 + ntp * 16
                               + ((lane >> 4) << 3) + (lane & 7));
                uint32_t bfr[4];
                ldsm4(base + OFF_B + rowB * PITCH
                      + ks * 32 + (((lane >> 3) & 1) << 4), bfr);
                if (FUSE) {
                    #pragma unroll
                    for (int j = 0; j < 4; j++) {
                        const float2 sc = (j & 1) ? scB : scA;
                        const float2 bs = (j & 1) ? bsB : bsA;
                        float2 v = __half22float2(*(__half2*)&bfr[j]);
                        v.x = fmaxf(fmaf(v.x, sc.x, bs.x), 0.0f);
                        v.y = fmaxf(fmaf(v.y, sc.y, bs.y), 0.0f);
                        *(__half2*)&bfr[j] = __floats2half2_rn(v.x, v.y);
                    }
                }
                #pragma unroll
                for (int h = 0; h < 2; h++) {
                    int nt = ntp * 2 + h;
                    #pragma unroll
                    for (int mt = 0; mt < 4; mt++)
                        mma16816(acc[mt][nt], a[mt], &bfr[h * 2]);
                }
            }
        }
        __syncthreads();
    }

    // ---- epilogue: bias, BN partials, smem-staged fp16 coalesced flush -------
    float* sy = (float*)sdyn;             // [64][260] per N-half
    const int r = lane >> 2;
    float csum[8] = {}, cssq[8] = {};

    #pragma unroll
    for (int half = 0; half < 2; half++) {
        if (nw == half) {
            #pragma unroll
            for (int mt = 0; mt < 4; mt++) {
                const int m0 = mw * 64 + mt * 16 + r;
                const int m1 = m0 + 8;
                const float bv0 = bias[m0], bv1 = bias[m1];
                #pragma unroll
                for (int nt = 0; nt < 8; nt++) {
                    float* c = acc[mt][nt];
                    int nl = nt * 8 + (lane & 3) * 2;
                    float v0 = c[0] + bv0, v1 = c[1] + bv0;
                    float v2 = c[2] + bv1, v3 = c[3] + bv1;
                    sy[nl * 260 + m0]       = v0;
                    sy[(nl + 1) * 260 + m0] = v1;
                    sy[nl * 260 + m1]       = v2;
                    sy[(nl + 1) * 260 + m1] = v3;
                    csum[mt * 2]     += v0 + v1;
                    cssq[mt * 2]     += fmaf(v0, v0, v1 * v1);
                    csum[mt * 2 + 1] += v2 + v3;
                    cssq[mt * 2 + 1] += fmaf(v2, v2, v3 * v3);
                }
            }
        }
        __syncthreads();
        // coalesced fp16 flush: 64 rows x 512B, two rows per iteration
        #pragma unroll 8
        for (int i = 0; i < 32; i++) {
            int row = i * 2 + (tid >> 7);
            int c2  = tid & 127;
            __half2 hp = __floats2half2_rn(sy[row * 260 + c2 * 2],
                                           sy[row * 260 + c2 * 2 + 1]);
            *(__half2*)(Y + (bn0 + half * 64 + row) * 256 + c2 * 2) = hp;
        }
        __syncthreads();
    }

    // BN partials
    #pragma unroll
    for (int j = 0; j < 8; j++) {
        csum[j] += __shfl_xor_sync(0xffffffffu, csum[j], 1);
        csum[j] += __shfl_xor_sync(0xffffffffu, csum[j], 2);
        cssq[j] += __shfl_xor_sync(0xffffffffu, cssq[j], 1);
        cssq[j] += __shfl_xor_sync(0xffffffffu, cssq[j], 2);
    }
    if ((lane & 3) == 0) {
        #pragma unroll
        for (int mt = 0; mt < 4; mt++) {
            #pragma unroll
            for (int h = 0; h < 2; h++) {
                int ch = mw * 64 + mt * 16 + r + h * 8;
                sm_s[nw][ch] = csum[mt * 2 + h];
                sm_q[nw][ch] = cssq[mt * 2 + h];
            }
        }
    }
    __syncthreads();
    {
        int cta = blockIdx.x + blockIdx.y * gridDim.x;
        psum[tid * 1024 + cta] = sm_s[0][tid] + sm_s[1][tid];
        pssq[tid * 1024 + cta] = sm_q[0][tid] + sm_q[1][tid];
    }
}

// ---------------- BN fold: reduce 1024 partials per channel -------------------
__global__ __launch_bounds__(256) void stats2_kernel(
    const float* __restrict__ g, const float* __restrict__ beta,
    float* __restrict__ sb)
{
    const int o = blockIdx.x;
    const int t = threadIdx.x;
    float s = 0.0f, ss = 0.0f;
    #pragma unroll
    for (int i = 0; i < 4; i++) {
        s  += g_psum[o * 1024 + t * 4 + i];
        ss += g_pssq[o * 1024 + t * 4 + i];
    }
    const int lane = t & 31, w = t >> 5;
    #pragma unroll
    for (int off = 16; off; off >>= 1) {
        s  += __shfl_down_sync(0xffffffffu, s,  off);
        ss += __shfl_down_sync(0xffffffffu, ss, off);
    }
    __shared__ float rs[8], rss[8];
    if (lane == 0) { rs[w] = s; rss[w] = ss; }
    __syncthreads();
    if (t == 0) {
        float ts = 0.0f, tss = 0.0f;
        #pragma unroll
        for (int i = 0; i < 8; i++) { ts += rs[i]; tss += rss[i]; }
        float mean = ts * CNT_INV;
        float var  = tss * CNT_INV - mean * mean;
        float rstd = rsqrtf(var + BN_EPS);
        float sc = g[o] * rstd;
        sb[o]       = sc;
        sb[256 + o] = beta[o] - mean * sc;
    }
}

// ---------------- final norm + relu + transpose -> out [B][256][N] ------------
// Tile: 32 n-rows x 64 m. half2 loads (128B rows), fp32 writes (128B rows).
__global__ __launch_bounds__(256) void outt_kernel(
    const __half* __restrict__ y, const float* __restrict__ sb,
    float* __restrict__ out)
{
    __shared__ float tile[32][65];
    const int b  = blockIdx.z;
    const int n0 = blockIdx.x * 32;
    const int m0 = blockIdx.y * 64;
    const int tx = threadIdx.x;      // 0..31
    const int ty = threadIdx.y;      // 0..7
    #pragma unroll
    for (int r = 0; r < 4; r++) {
        int n = n0 + ty + r * 8;
        __half2 hv = *(const __half2*)(y + ((size_t)b * N_ + n) * 256 + m0 + tx * 2);
        float2 f = __half22float2(hv);
        tile[ty + r * 8][tx * 2]     = f.x;
        tile[ty + r * 8][tx * 2 + 1] = f.y;
    }
    __syncthreads();
    #pragma unroll
    for (int r = 0; r < 8; r++) {
        int m = m0 + ty + r * 8;
        float sc = sb[m], bs = sb[256 + m];
        out[((size_t)b * 256 + m) * N_ + n0 + tx] =
            fmaxf(fmaf(tile[tx][ty + r * 8], sc, bs), 0.0f);
    }
}

// ---------------- launcher ----------------------------------------------------
extern "C" void kernel_launch(void* const* d_in, const int* in_sizes, int n_in,
                              void* d_out, int out_size)
{
    const float* xyz1 = (const float*)d_in[0];
    const float* xyz2 = (const float*)d_in[1];
    const float* pts1 = (const float*)d_in[2];
    const float* pts2 = (const float*)d_in[3];
    const float* W0   = (const float*)d_in[4];
    const float* b0   = (const float*)d_in[5];
    const float* gg0  = (const float*)d_in[6];
    const float* be0  = (const float*)d_in[7];
    const float* W1   = (const float*)d_in[8];
    const float* b1   = (const float*)d_in[9];
    const float* gg1  = (const float*)d_in[10];
    const float* be1  = (const float*)d_in[11];
    float* out = (float*)d_out;

    __half *xq, *w0q, *w1q, *y;
    float *psum, *pssq, *sb1, *sb2;
    cudaGetSymbolAddress((void**)&xq,  g_xq);
    cudaGetSymbolAddress((void**)&w0q, g_w0q);
    cudaGetSymbolAddress((void**)&w1q, g_w1q);
    cudaGetSymbolAddress((void**)&y,   g_y);
    cudaGetSymbolAddress((void**)&psum, g_psum);
    cudaGetSymbolAddress((void**)&pssq, g_pssq);
    cudaGetSymbolAddress((void**)&sb1, g_sb1);
    cudaGetSymbolAddress((void**)&sb2, g_sb2);

    const int GEMM_SMEM = 68096;   // max(2 stages 61440, sy 64*260*4=66560) +pad
    cudaFuncSetAttribute(gemm_mma<K1_, false>, cudaFuncAttributeMaxDynamicSharedMemorySize, GEMM_SMEM);
    cudaFuncSetAttribute(gemm_mma<O_,  true >, cudaFuncAttributeMaxDynamicSharedMemorySize, GEMM_SMEM);

    // prep
    wconv_kernel<<<(O_ * K1_ + 255) / 256, 256>>>(W0, w0q, O_ * K1_);
    wconv_kernel<<<(O_ * O_  + 255) / 256, 256>>>(W1, w1q, O_ * O_);
    knn_kernel<<<dim3(N_ / 2048, B_), 256>>>(xyz1, xyz2);
    transpose_p2_kernel<<<dim3(S_ / 32, C2_ / 32, B_), dim3(32, 8)>>>(pts2);
    gather_kernel<<<dim3(N_ / 32, B_), 256>>>();
    p1t_kernel<<<dim3(N_ / 32, C1_ / 32, B_), dim3(32, 8)>>>(pts1);

    // layer 1 -> y1
    gemm_mma<K1_, false><<<dim3(N_ / 128, B_), 256, GEMM_SMEM>>>(
        w0q, xq, b0, y, psum, pssq, nullptr);
    stats2_kernel<<<256, 256>>>(gg0, be0, sb1);

    // layer 2: reads raw y1, fp32 norm+relu on B fragments, writes y2 in place
    gemm_mma<O_, true><<<dim3(N_ / 128, B_), 256, GEMM_SMEM>>>(
        w1q, y, b1, y, psum, pssq, sb1);
    stats2_kernel<<<256, 256>>>(gg1, be1, sb2);

    // output
    outt_kernel<<<dim3(N_ / 32, 4, B_), dim3(32, 8)>>>(y, sb2, out);
}

// round 13
// speedup vs baseline: 1.6011x; 1.3590x over previous
#include <cuda_runtime.h>
#include <cuda_fp16.h>
#include <cstdint>

static constexpr int B_  = 8;
static constexpr int N_  = 16384;
static constexpr int S_  = 2048;
static constexpr int C1_ = 128;
static constexpr int C2_ = 256;
static constexpr int K1_ = 384;
static constexpr int O_  = 256;
static constexpr float BN_EPS  = 1e-5f;
static constexpr float CNT_INV = 1.0f / (float)(B_ * N_);

// ---------------- device-global scratch (no cudaMalloc allowed) ---------------
__device__ __half g_xq[(size_t)B_ * N_ * K1_];   // concat input, fp16 [n][k]
__device__ __half g_y [(size_t)B_ * N_ * O_];    // y1 then y2, fp16 (n-major)
__device__ float  g_p2t[(size_t)B_ * S_ * C2_];  // points2 transposed [B][S][C]
__device__ int    g_idx[(size_t)B_ * N_ * 3];
__device__ float  g_w  [(size_t)B_ * N_ * 3];
__device__ __half g_w0q[O_ * K1_];               // W0 fp16
__device__ __half g_w1q[O_ * O_];                // W1 fp16
__device__ float  g_psum[256 * 1024], g_pssq[256 * 1024];
__device__ float  g_sb1[512], g_sb2[512];

// ---------------- small PTX helpers ------------------------------------------
__device__ __forceinline__ uint32_t smem_u32(const void* p) {
    uint32_t a;
    asm("{ .reg .u64 t; cvta.to.shared.u64 t, %1; cvt.u32.u64 %0, t; }"
        : "=r"(a) : "l"(p));
    return a;
}
__device__ __forceinline__ void cpa16(uint32_t dst, const void* src) {
    asm volatile("cp.async.cg.shared.global [%0], [%1], 16;"
                 :: "r"(dst), "l"(src) : "memory");
}
#define CP_COMMIT() asm volatile("cp.async.commit_group;" ::: "memory")
#define CP_WAIT0()  asm volatile("cp.async.wait_group 0;" ::: "memory")
#define CP_WAIT1()  asm volatile("cp.async.wait_group 1;" ::: "memory")

__device__ __forceinline__ void ldsm4(uint32_t addr, uint32_t* r) {
    asm volatile("ldmatrix.sync.aligned.m8n8.x4.shared.b16 {%0,%1,%2,%3}, [%4];"
                 : "=r"(r[0]), "=r"(r[1]), "=r"(r[2]), "=r"(r[3]) : "r"(addr));
}
__device__ __forceinline__ void mma16816(float* c, const uint32_t* a, const uint32_t* b) {
    asm volatile(
        "mma.sync.aligned.m16n8k16.row.col.f32.f16.f16.f32 "
        "{%0,%1,%2,%3}, {%4,%5,%6,%7}, {%8,%9}, {%0,%1,%2,%3};"
        : "+f"(c[0]), "+f"(c[1]), "+f"(c[2]), "+f"(c[3])
        : "r"(a[0]), "r"(a[1]), "r"(a[2]), "r"(a[3]), "r"(b[0]), "r"(b[1]));
}

// ---------------- kNN (4 queries per thread, exact squared distances) ---------
__global__ __launch_bounds__(256) void knn_kernel(
    const float* __restrict__ xyz1, const float* __restrict__ xyz2)
{
    __shared__ float4 sp[S_];
    const int b = blockIdx.y;
    const int t = threadIdx.x;
    for (int s = t; s < S_; s += 256) {
        const float* p = xyz2 + ((size_t)b * S_ + s) * 3;
        sp[s] = make_float4(p[0], p[1], p[2], 0.0f);
    }
    __syncthreads();

    const int nb = blockIdx.x * 1024 + t;
    float qx[4], qy[4], qz[4];
    float d0[4], d1[4], d2[4];
    int   i0[4], i1[4], i2[4];
    #pragma unroll
    for (int j = 0; j < 4; j++) {
        const float* q = xyz1 + ((size_t)b * N_ + nb + j * 256) * 3;
        qx[j] = q[0]; qy[j] = q[1]; qz[j] = q[2];
        d0[j] = 3.4e38f; d1[j] = 3.4e38f; d2[j] = 3.4e38f;
        i0[j] = 0; i1[j] = 0; i2[j] = 0;
    }
    #pragma unroll 2
    for (int s = 0; s < S_; s++) {
        float4 p = sp[s];
        #pragma unroll
        for (int j = 0; j < 4; j++) {
            float dx = qx[j] - p.x, dy = qy[j] - p.y, dz = qz[j] - p.z;
            float d = fmaf(dz, dz, fmaf(dy, dy, dx * dx));
            if (d < d2[j]) {
                if (d < d1[j]) {
                    d2[j] = d1[j]; i2[j] = i1[j];
                    if (d < d0[j]) { d1[j] = d0[j]; i1[j] = i0[j]; d0[j] = d; i0[j] = s; }
                    else           { d1[j] = d;  i1[j] = s; }
                } else { d2[j] = d; i2[j] = s; }
            }
        }
    }
    #pragma unroll
    for (int j = 0; j < 4; j++) {
        float a = fmaxf(d0[j], 1e-10f), bb = fmaxf(d1[j], 1e-10f), c = fmaxf(d2[j], 1e-10f);
        float w0 = 1.0f / a, w1 = 1.0f / bb, w2 = 1.0f / c;
        float sw = w0 + w1 + w2;
        size_t base = ((size_t)b * N_ + nb + j * 256) * 3;
        g_idx[base] = i0[j]; g_idx[base + 1] = i1[j]; g_idx[base + 2] = i2[j];
        g_w[base] = w0 / sw; g_w[base + 1] = w1 / sw; g_w[base + 2] = w2 / sw;
    }
}

// ---------------- transpose points2 [B][C][S] -> [B][S][C] --------------------
__global__ void transpose_p2_kernel(const float* __restrict__ p2)
{
    __shared__ float tile[32][33];
    const int b  = blockIdx.z;
    const int s0 = blockIdx.x * 32;
    const int c0 = blockIdx.y * 32;
    #pragma unroll
    for (int r = 0; r < 4; r++) {
        int c = c0 + threadIdx.y + r * 8;
        tile[threadIdx.y + r * 8][threadIdx.x] =
            p2[((size_t)b * C2_ + c) * S_ + s0 + threadIdx.x];
    }
    __syncthreads();
    #pragma unroll
    for (int r = 0; r < 4; r++) {
        int s = s0 + threadIdx.y + r * 8;
        g_p2t[((size_t)b * S_ + s) * C2_ + c0 + threadIdx.x] =
            tile[threadIdx.x][threadIdx.y + r * 8];
    }
}

// ---------------- gather + weighted sum -> xcat channels [0,256) --------------
// 256 thr = 128 channel-pairs x 2 n-points; float2 reads, half2 writes.
__global__ __launch_bounds__(256) void gather_kernel()
{
    const int b  = blockIdx.y;
    const int n0 = blockIdx.x * 32;
    const int cp = threadIdx.x & 127;    // channel pair
    const int no = threadIdx.x >> 7;     // n offset 0/1
    #pragma unroll 2
    for (int it = 0; it < 16; it++) {
        int nl = it * 2 + no;
        size_t base = ((size_t)b * N_ + n0 + nl) * 3;
        int i0 = g_idx[base], i1 = g_idx[base + 1], i2 = g_idx[base + 2];
        float w0 = g_w[base], w1 = g_w[base + 1], w2 = g_w[base + 2];
        const float2* r0 = (const float2*)(g_p2t + ((size_t)b * S_ + i0) * C2_);
        const float2* r1 = (const float2*)(g_p2t + ((size_t)b * S_ + i1) * C2_);
        const float2* r2 = (const float2*)(g_p2t + ((size_t)b * S_ + i2) * C2_);
        float2 a0 = r0[cp], a1 = r1[cp], a2 = r2[cp];
        float v0 = fmaf(w2, a2.x, fmaf(w1, a1.x, w0 * a0.x));
        float v1 = fmaf(w2, a2.y, fmaf(w1, a1.y, w0 * a0.y));
        *(__half2*)(g_xq + ((size_t)b * N_ + n0 + nl) * K1_ + cp * 2) =
            __floats2half2_rn(v0, v1);
    }
}

// ---------------- points1 transpose -> xcat channels [256,384) ----------------
__global__ void p1t_kernel(const float* __restrict__ p1)
{
    __shared__ float tile[32][33];
    const int b  = blockIdx.z;
    const int n0 = blockIdx.x * 32;
    const int c0 = blockIdx.y * 32;
    #pragma unroll
    for (int r = 0; r < 4; r++) {
        int c = c0 + threadIdx.y + r * 8;
        tile[threadIdx.y + r * 8][threadIdx.x] =
            p1[((size_t)b * C1_ + c) * N_ + n0 + threadIdx.x];
    }
    __syncthreads();
    #pragma unroll
    for (int r = 0; r < 4; r++) {
        int n = n0 + threadIdx.y + r * 8;
        float v = tile[threadIdx.x][threadIdx.y + r * 8];
        g_xq[((size_t)b * N_ + n) * K1_ + 256 + c0 + threadIdx.x] = __float2half_rn(v);
    }
}

// ---------------- weight fp16 convert -----------------------------------------
__global__ void wconv_kernel(const float* __restrict__ w,
                             __half* __restrict__ q, int n)
{
    int i = blockIdx.x * 256 + threadIdx.x;
    if (i < n) q[i] = __float2half_rn(w[i]);
}

// ---------------- mma.sync fp16 GEMM (R10 2-stage structure) ------------------
// FUSE=0: D = W @ X             (layer 1; X = g_xq)
// FUSE=1: D = W @ relu(sc*X+bs) (layer 2; X = raw y1; affine in fp32 on B frags)
// CTA: 256 thr = 8 warps (4 in M x 2 in N). Warp tile 64x64.
// Epilogue: BN partials from fp32 accs; y stored fp16 via smem-staged flush.
template<int KDIM, bool FUSE>
__global__ __launch_bounds__(256) void gemm_mma(
    const __half* __restrict__ Aq, const __half* __restrict__ Bq,
    const float* __restrict__ bias, __half* __restrict__ Y,
    float* __restrict__ psum, float* __restrict__ pssq,
    const float* __restrict__ sbn)
{
    constexpr int NS = KDIM / 32;                 // K stages of 32
    constexpr uint32_t PITCH  = 80;               // 64B data + 16B pad
    constexpr uint32_t OFF_B  = 256u * PITCH;     // 20480
    constexpr uint32_t STAGE  = OFF_B + 128u * PITCH;  // 30720

    extern __shared__ char sdyn[];
    __shared__ float sm_s[2][256], sm_q[2][256];
    __shared__ float2 sscf[128], sbbf[128];       // fp32 per-channel-pair scale/bias

    const int tid  = threadIdx.x;
    const int lane = tid & 31, wid = tid >> 5;
    const int mw   = wid & 3;        // M block of 64
    const int nw   = wid >> 2;       // N block of 64
    const int b    = blockIdx.y;
    const int n0   = blockIdx.x * 128;
    const size_t bn0 = (size_t)b * N_ + n0;
    const uint32_t sb0 = smem_u32(sdyn);

    if (FUSE && tid < 128) {
        sscf[tid] = make_float2(sbn[2 * tid], sbn[2 * tid + 1]);
        sbbf[tid] = make_float2(sbn[256 + 2 * tid], sbn[256 + 2 * tid + 1]);
    }

    auto load_stage = [&](int kt, int buf) {
        uint32_t base = sb0 + (uint32_t)buf * STAGE;
        #pragma unroll
        for (int i = 0; i < 4; i++) {              // A: 256 rows x 4 chunks
            int c = tid + i * 256;
            int row = (c >> 2) & 255, ch = c & 3;
            const __half* src = Aq + (size_t)row * KDIM + kt + ch * 8;
            cpa16(base + (uint32_t)row * PITCH + ch * 16, src);
        }
        #pragma unroll
        for (int i = 0; i < 2; i++) {              // B: 128 rows x 4 chunks
            int c = tid + i * 256;
            int row = (c >> 2) & 127, ch = c & 3;
            const __half* src = Bq + (bn0 + row) * KDIM + kt + ch * 8;
            cpa16(base + OFF_B + (uint32_t)row * PITCH + ch * 16, src);
        }
        CP_COMMIT();
    };

    float acc[4][8][4] = {};

    load_stage(0, 0);

    #pragma unroll 1
    for (int s = 0; s < NS; s++) {
        if (s + 1 < NS) { load_stage((s + 1) * 32, (s + 1) & 1); CP_WAIT1(); }
        else            { CP_WAIT0(); }
        __syncthreads();

        uint32_t base = sb0 + (uint32_t)(s & 1) * STAGE;
        #pragma unroll
        for (int ks = 0; ks < 2; ks++) {
            uint32_t a[4][4];
            #pragma unroll
            for (int mt = 0; mt < 4; mt++) {
                uint32_t row = (uint32_t)(mw * 64 + mt * 16 + (lane & 15));
                ldsm4(base + row * PITCH + ks * 32 + ((lane >> 4) << 4), a[mt]);
            }
            // fp32 per-k scale/bias for this thread's B fragment positions
            float2 scA, scB, bsA, bsB;
            if (FUSE) {
                int kp = s * 16 + ks * 8 + (lane & 3);
                scA = sscf[kp];     bsA = sbbf[kp];
                scB = sscf[kp + 4]; bsB = sbbf[kp + 4];
            }
            #pragma unroll
            for (int ntp = 0; ntp < 4; ntp++) {
                uint32_t rowB = (uint32_t)(nw * 64 + ntp * 16
                               + ((lane >> 4) << 3) + (lane & 7));
                uint32_t bfr[4];
                ldsm4(base + OFF_B + rowB * PITCH
                      + ks * 32 + (((lane >> 3) & 1) << 4), bfr);
                if (FUSE) {
                    #pragma unroll
                    for (int j = 0; j < 4; j++) {
                        const float2 sc = (j & 1) ? scB : scA;
                        const float2 bs = (j & 1) ? bsB : bsA;
                        float2 v = __half22float2(*(__half2*)&bfr[j]);
                        v.x = fmaxf(fmaf(v.x, sc.x, bs.x), 0.0f);
                        v.y = fmaxf(fmaf(v.y, sc.y, bs.y), 0.0f);
                        *(__half2*)&bfr[j] = __floats2half2_rn(v.x, v.y);
                    }
                }
                #pragma unroll
                for (int h = 0; h < 2; h++) {
                    int nt = ntp * 2 + h;
                    #pragma unroll
                    for (int mt = 0; mt < 4; mt++)
                        mma16816(acc[mt][nt], a[mt], &bfr[h * 2]);
                }
            }
        }
        __syncthreads();
    }

    // ---- epilogue: bias, BN partials, smem-staged fp16 coalesced flush -------
    float* sy = (float*)sdyn;             // [64][260] per N-half
    const int r = lane >> 2;
    float csum[8] = {}, cssq[8] = {};

    #pragma unroll
    for (int half = 0; half < 2; half++) {
        if (nw == half) {
            #pragma unroll
            for (int mt = 0; mt < 4; mt++) {
                const int m0 = mw * 64 + mt * 16 + r;
                const int m1 = m0 + 8;
                const float bv0 = bias[m0], bv1 = bias[m1];
                #pragma unroll
                for (int nt = 0; nt < 8; nt++) {
                    float* c = acc[mt][nt];
                    int nl = nt * 8 + (lane & 3) * 2;
                    float v0 = c[0] + bv0, v1 = c[1] + bv0;
                    float v2 = c[2] + bv1, v3 = c[3] + bv1;
                    sy[nl * 260 + m0]       = v0;
                    sy[(nl + 1) * 260 + m0] = v1;
                    sy[nl * 260 + m1]       = v2;
                    sy[(nl + 1) * 260 + m1] = v3;
                    csum[mt * 2]     += v0 + v1;
                    cssq[mt * 2]     += fmaf(v0, v0, v1 * v1);
                    csum[mt * 2 + 1] += v2 + v3;
                    cssq[mt * 2 + 1] += fmaf(v2, v2, v3 * v3);
                }
            }
        }
        __syncthreads();
        // coalesced fp16 flush: 64 rows x 512B, two rows per iteration
        #pragma unroll 8
        for (int i = 0; i < 32; i++) {
            int row = i * 2 + (tid >> 7);
            int c2  = tid & 127;
            __half2 hp = __floats2half2_rn(sy[row * 260 + c2 * 2],
                                           sy[row * 260 + c2 * 2 + 1]);
            *(__half2*)(Y + (bn0 + half * 64 + row) * 256 + c2 * 2) = hp;
        }
        __syncthreads();
    }

    // BN partials
    #pragma unroll
    for (int j = 0; j < 8; j++) {
        csum[j] += __shfl_xor_sync(0xffffffffu, csum[j], 1);
        csum[j] += __shfl_xor_sync(0xffffffffu, csum[j], 2);
        cssq[j] += __shfl_xor_sync(0xffffffffu, cssq[j], 1);
        cssq[j] += __shfl_xor_sync(0xffffffffu, cssq[j], 2);
    }
    if ((lane & 3) == 0) {
        #pragma unroll
        for (int mt = 0; mt < 4; mt++) {
            #pragma unroll
            for (int h = 0; h < 2; h++) {
                int ch = mw * 64 + mt * 16 + r + h * 8;
                sm_s[nw][ch] = csum[mt * 2 + h];
                sm_q[nw][ch] = cssq[mt * 2 + h];
            }
        }
    }
    __syncthreads();
    {
        int cta = blockIdx.x + blockIdx.y * gridDim.x;
        psum[tid * 1024 + cta] = sm_s[0][tid] + sm_s[1][tid];
        pssq[tid * 1024 + cta] = sm_q[0][tid] + sm_q[1][tid];
    }
}

// ---------------- BN fold: reduce 1024 partials per channel -------------------
__global__ __launch_bounds__(256) void stats2_kernel(
    const float* __restrict__ g, const float* __restrict__ beta,
    float* __restrict__ sb)
{
    const int o = blockIdx.x;
    const int t = threadIdx.x;
    float s = 0.0f, ss = 0.0f;
    #pragma unroll
    for (int i = 0; i < 4; i++) {
        s  += g_psum[o * 1024 + t * 4 + i];
        ss += g_pssq[o * 1024 + t * 4 + i];
    }
    const int lane = t & 31, w = t >> 5;
    #pragma unroll
    for (int off = 16; off; off >>= 1) {
        s  += __shfl_down_sync(0xffffffffu, s,  off);
        ss += __shfl_down_sync(0xffffffffu, ss, off);
    }
    __shared__ float rs[8], rss[8];
    if (lane == 0) { rs[w] = s; rss[w] = ss; }
    __syncthreads();
    if (t == 0) {
        float ts = 0.0f, tss = 0.0f;
        #pragma unroll
        for (int i = 0; i < 8; i++) { ts += rs[i]; tss += rss[i]; }
        float mean = ts * CNT_INV;
        float var  = tss * CNT_INV - mean * mean;
        float rstd = rsqrtf(var + BN_EPS);
        float sc = g[o] * rstd;
        sb[o]       = sc;
        sb[256 + o] = beta[o] - mean * sc;
    }
}

// ---------------- final norm + relu + transpose -> out [B][256][N] ------------
// Tile: 32 n-rows x 64 m. half2 loads (128B rows), fp32 writes (128B rows).
__global__ __launch_bounds__(256) void outt_kernel(
    const __half* __restrict__ y, const float* __restrict__ sb,
    float* __restrict__ out)
{
    __shared__ float tile[32][65];
    const int b  = blockIdx.z;
    const int n0 = blockIdx.x * 32;
    const int m0 = blockIdx.y * 64;
    const int tx = threadIdx.x;      // 0..31
    const int ty = threadIdx.y;      // 0..7
    #pragma unroll
    for (int r = 0; r < 4; r++) {
        int n = n0 + ty + r * 8;
        __half2 hv = *(const __half2*)(y + ((size_t)b * N_ + n) * 256 + m0 + tx * 2);
        float2 f = __half22float2(hv);
        tile[ty + r * 8][tx * 2]     = f.x;
        tile[ty + r * 8][tx * 2 + 1] = f.y;
    }
    __syncthreads();
    #pragma unroll
    for (int r = 0; r < 8; r++) {
        int m = m0 + ty + r * 8;
        float sc = sb[m], bs = sb[256 + m];
        out[((size_t)b * 256 + m) * N_ + n0 + tx] =
            fmaxf(fmaf(tile[tx][ty + r * 8], sc, bs), 0.0f);
    }
}

// ---------------- launcher ----------------------------------------------------
extern "C" void kernel_launch(void* const* d_in, const int* in_sizes, int n_in,
                              void* d_out, int out_size)
{
    const float* xyz1 = (const float*)d_in[0];
    const float* xyz2 = (const float*)d_in[1];
    const float* pts1 = (const float*)d_in[2];
    const float* pts2 = (const float*)d_in[3];
    const float* W0   = (const float*)d_in[4];
    const float* b0   = (const float*)d_in[5];
    const float* gg0  = (const float*)d_in[6];
    const float* be0  = (const float*)d_in[7];
    const float* W1   = (const float*)d_in[8];
    const float* b1   = (const float*)d_in[9];
    const float* gg1  = (const float*)d_in[10];
    const float* be1  = (const float*)d_in[11];
    float* out = (float*)d_out;

    __half *xq, *w0q, *w1q, *y;
    float *psum, *pssq, *sb1, *sb2;
    cudaGetSymbolAddress((void**)&xq,  g_xq);
    cudaGetSymbolAddress((void**)&w0q, g_w0q);
    cudaGetSymbolAddress((void**)&w1q, g_w1q);
    cudaGetSymbolAddress((void**)&y,   g_y);
    cudaGetSymbolAddress((void**)&psum, g_psum);
    cudaGetSymbolAddress((void**)&pssq, g_pssq);
    cudaGetSymbolAddress((void**)&sb1, g_sb1);
    cudaGetSymbolAddress((void**)&sb2, g_sb2);

    const int GEMM_SMEM = 68096;   // max(2 stages 61440, sy 64*260*4=66560) +pad
    cudaFuncSetAttribute(gemm_mma<K1_, false>, cudaFuncAttributeMaxDynamicSharedMemorySize, GEMM_SMEM);
    cudaFuncSetAttribute(gemm_mma<O_,  true >, cudaFuncAttributeMaxDynamicSharedMemorySize, GEMM_SMEM);

    // prep
    wconv_kernel<<<(O_ * K1_ + 255) / 256, 256>>>(W0, w0q, O_ * K1_);
    wconv_kernel<<<(O_ * O_  + 255) / 256, 256>>>(W1, w1q, O_ * O_);
    knn_kernel<<<dim3(N_ / 1024, B_), 256>>>(xyz1, xyz2);
    transpose_p2_kernel<<<dim3(S_ / 32, C2_ / 32, B_), dim3(32, 8)>>>(pts2);
    gather_kernel<<<dim3(N_ / 32, B_), 256>>>();
    p1t_kernel<<<dim3(N_ / 32, C1_ / 32, B_), dim3(32, 8)>>>(pts1);

    // layer 1 -> y1
    gemm_mma<K1_, false><<<dim3(N_ / 128, B_), 256, GEMM_SMEM>>>(
        w0q, xq, b0, y, psum, pssq, nullptr);
    stats2_kernel<<<256, 256>>>(gg0, be0, sb1);

    // layer 2: reads raw y1, fp32 norm+relu on B fragments, writes y2 in place
    gemm_mma<O_, true><<<dim3(N_ / 128, B_), 256, GEMM_SMEM>>>(
        w1q, y, b1, y, psum, pssq, sb1);
    stats2_kernel<<<256, 256>>>(gg1, be1, sb2);

    // output
    outt_kernel<<<dim3(N_ / 32, 4, B_), dim3(32, 8)>>>(y, sb2, out);
}

// round 14
// speedup vs baseline: 2.0686x; 1.2920x over previous
#include <cuda_runtime.h>
#include <cuda_fp16.h>
#include <cstdint>

static constexpr int B_  = 8;
static constexpr int N_  = 16384;
static constexpr int S_  = 2048;
static constexpr int C1_ = 128;
static constexpr int C2_ = 256;
static constexpr int K1_ = 384;
static constexpr int O_  = 256;
static constexpr float BN_EPS  = 1e-5f;
static constexpr float CNT_INV = 1.0f / (float)(B_ * N_);

// ---------------- device-global scratch (no cudaMalloc allowed) ---------------
__device__ __half g_xq[(size_t)B_ * N_ * K1_];   // concat input, fp16 [n][k]
__device__ __half g_y [(size_t)B_ * N_ * O_];    // y1 then y2, fp16 (n-major)
__device__ float  g_p2t[(size_t)B_ * S_ * C2_];  // points2 transposed [B][S][C]
__device__ int    g_idx[(size_t)B_ * N_ * 3];
__device__ float  g_w  [(size_t)B_ * N_ * 3];
__device__ __half g_w0q[O_ * K1_];               // W0 fp16
__device__ __half g_w1q[O_ * O_];                // W1 fp16
__device__ float  g_psum[256 * 1024], g_pssq[256 * 1024];
__device__ float  g_sb1[512], g_sb2[512];

// ---------------- small PTX helpers ------------------------------------------
__device__ __forceinline__ uint32_t smem_u32(const void* p) {
    uint32_t a;
    asm("{ .reg .u64 t; cvta.to.shared.u64 t, %1; cvt.u32.u64 %0, t; }"
        : "=r"(a) : "l"(p));
    return a;
}
__device__ __forceinline__ void cpa16(uint32_t dst, const void* src) {
    asm volatile("cp.async.cg.shared.global [%0], [%1], 16;"
                 :: "r"(dst), "l"(src) : "memory");
}
#define CP_COMMIT() asm volatile("cp.async.commit_group;" ::: "memory")
#define CP_WAIT0()  asm volatile("cp.async.wait_group 0;" ::: "memory")
#define CP_WAIT1()  asm volatile("cp.async.wait_group 1;" ::: "memory")

__device__ __forceinline__ void ldsm4(uint32_t addr, uint32_t* r) {
    asm volatile("ldmatrix.sync.aligned.m8n8.x4.shared.b16 {%0,%1,%2,%3}, [%4];"
                 : "=r"(r[0]), "=r"(r[1]), "=r"(r[2]), "=r"(r[3]) : "r"(addr));
}
__device__ __forceinline__ void mma16816(float* c, const uint32_t* a, const uint32_t* b) {
    asm volatile(
        "mma.sync.aligned.m16n8k16.row.col.f32.f16.f16.f32 "
        "{%0,%1,%2,%3}, {%4,%5,%6,%7}, {%8,%9}, {%0,%1,%2,%3};"
        : "+f"(c[0]), "+f"(c[1]), "+f"(c[2]), "+f"(c[3])
        : "r"(a[0]), "r"(a[1]), "r"(a[2]), "r"(a[3]), "r"(b[0]), "r"(b[1]));
}

// ---------------- kNN (2 queries per thread, exact squared distances) ---------
__global__ __launch_bounds__(256) void knn_kernel(
    const float* __restrict__ xyz1, const float* __restrict__ xyz2)
{
    __shared__ float4 sp[S_];
    const int b = blockIdx.y;
    const int t = threadIdx.x;
    for (int s = t; s < S_; s += 256) {
        const float* p = xyz2 + ((size_t)b * S_ + s) * 3;
        sp[s] = make_float4(p[0], p[1], p[2], 0.0f);
    }
    __syncthreads();

    const int nb = blockIdx.x * 512 + t;
    float qx[2], qy[2], qz[2];
    float d0[2], d1[2], d2[2];
    int   i0[2], i1[2], i2[2];
    #pragma unroll
    for (int j = 0; j < 2; j++) {
        const float* q = xyz1 + ((size_t)b * N_ + nb + j * 256) * 3;
        qx[j] = q[0]; qy[j] = q[1]; qz[j] = q[2];
        d0[j] = 3.4e38f; d1[j] = 3.4e38f; d2[j] = 3.4e38f;
        i0[j] = 0; i1[j] = 0; i2[j] = 0;
    }
    #pragma unroll 4
    for (int s = 0; s < S_; s++) {
        float4 p = sp[s];
        #pragma unroll
        for (int j = 0; j < 2; j++) {
            float dx = qx[j] - p.x, dy = qy[j] - p.y, dz = qz[j] - p.z;
            float d = fmaf(dz, dz, fmaf(dy, dy, dx * dx));
            if (d < d2[j]) {
                if (d < d1[j]) {
                    d2[j] = d1[j]; i2[j] = i1[j];
                    if (d < d0[j]) { d1[j] = d0[j]; i1[j] = i0[j]; d0[j] = d; i0[j] = s; }
                    else           { d1[j] = d;  i1[j] = s; }
                } else { d2[j] = d; i2[j] = s; }
            }
        }
    }
    #pragma unroll
    for (int j = 0; j < 2; j++) {
        float a = fmaxf(d0[j], 1e-10f), bb = fmaxf(d1[j], 1e-10f), c = fmaxf(d2[j], 1e-10f);
        float w0 = 1.0f / a, w1 = 1.0f / bb, w2 = 1.0f / c;
        float sw = w0 + w1 + w2;
        size_t base = ((size_t)b * N_ + nb + j * 256) * 3;
        g_idx[base] = i0[j]; g_idx[base + 1] = i1[j]; g_idx[base + 2] = i2[j];
        g_w[base] = w0 / sw; g_w[base + 1] = w1 / sw; g_w[base + 2] = w2 / sw;
    }
}

// ---------------- transpose points2 [B][C][S] -> [B][S][C] --------------------
__global__ void transpose_p2_kernel(const float* __restrict__ p2)
{
    __shared__ float tile[32][33];
    const int b  = blockIdx.z;
    const int s0 = blockIdx.x * 32;
    const int c0 = blockIdx.y * 32;
    #pragma unroll
    for (int r = 0; r < 4; r++) {
        int c = c0 + threadIdx.y + r * 8;
        tile[threadIdx.y + r * 8][threadIdx.x] =
            p2[((size_t)b * C2_ + c) * S_ + s0 + threadIdx.x];
    }
    __syncthreads();
    #pragma unroll
    for (int r = 0; r < 4; r++) {
        int s = s0 + threadIdx.y + r * 8;
        g_p2t[((size_t)b * S_ + s) * C2_ + c0 + threadIdx.x] =
            tile[threadIdx.x][threadIdx.y + r * 8];
    }
}

// ---------------- gather + weighted sum -> xcat channels [0,256) --------------
// 256 thr = 128 channel-pairs x 2 n-points; float2 reads, half2 writes.
__global__ __launch_bounds__(256) void gather_kernel()
{
    const int b  = blockIdx.y;
    const int n0 = blockIdx.x * 32;
    const int cp = threadIdx.x & 127;    // channel pair
    const int no = threadIdx.x >> 7;     // n offset 0/1
    #pragma unroll 2
    for (int it = 0; it < 16; it++) {
        int nl = it * 2 + no;
        size_t base = ((size_t)b * N_ + n0 + nl) * 3;
        int i0 = g_idx[base], i1 = g_idx[base + 1], i2 = g_idx[base + 2];
        float w0 = g_w[base], w1 = g_w[base + 1], w2 = g_w[base + 2];
        const float2* r0 = (const float2*)(g_p2t + ((size_t)b * S_ + i0) * C2_);
        const float2* r1 = (const float2*)(g_p2t + ((size_t)b * S_ + i1) * C2_);
        const float2* r2 = (const float2*)(g_p2t + ((size_t)b * S_ + i2) * C2_);
        float2 a0 = r0[cp], a1 = r1[cp], a2 = r2[cp];
        float v0 = fmaf(w2, a2.x, fmaf(w1, a1.x, w0 * a0.x));
        float v1 = fmaf(w2, a2.y, fmaf(w1, a1.y, w0 * a0.y));
        *(__half2*)(g_xq + ((size_t)b * N_ + n0 + nl) * K1_ + cp * 2) =
            __floats2half2_rn(v0, v1);
    }
}

// ---------------- points1 transpose -> xcat channels [256,384) ----------------
__global__ void p1t_kernel(const float* __restrict__ p1)
{
    __shared__ float tile[32][33];
    const int b  = blockIdx.z;
    const int n0 = blockIdx.x * 32;
    const int c0 = blockIdx.y * 32;
    #pragma unroll
    for (int r = 0; r < 4; r++) {
        int c = c0 + threadIdx.y + r * 8;
        tile[threadIdx.y + r * 8][threadIdx.x] =
            p1[((size_t)b * C1_ + c) * N_ + n0 + threadIdx.x];
    }
    __syncthreads();
    #pragma unroll
    for (int r = 0; r < 4; r++) {
        int n = n0 + threadIdx.y + r * 8;
        float v = tile[threadIdx.x][threadIdx.y + r * 8];
        g_xq[((size_t)b * N_ + n) * K1_ + 256 + c0 + threadIdx.x] = __float2half_rn(v);
    }
}

// ---------------- weight fp16 convert -----------------------------------------
__global__ void wconv_kernel(const float* __restrict__ w,
                             __half* __restrict__ q, int n)
{
    int i = blockIdx.x * 256 + threadIdx.x;
    if (i < n) q[i] = __float2half_rn(w[i]);
}

// ---------------- mma.sync fp16 GEMM (16 warps, warp tile 64x32) --------------
// FUSE=0: D = W @ X             (layer 1; X = g_xq)
// FUSE=1: D = W @ relu(sc*X+bs) (layer 2; X = raw y1; affine in fp32 on B frags)
// CTA: 512 thr = 16 warps (4 in M x 4 in N). CTA tile M=256 x N=128.
// Epilogue: BN partials from fp32 accs; y stored fp16 via smem-staged flush.
template<int KDIM, bool FUSE>
__global__ __launch_bounds__(512) void gemm_mma(
    const __half* __restrict__ Aq, const __half* __restrict__ Bq,
    const float* __restrict__ bias, __half* __restrict__ Y,
    float* __restrict__ psum, float* __restrict__ pssq,
    const float* __restrict__ sbn)
{
    constexpr int NS = KDIM / 32;                 // K stages of 32
    constexpr uint32_t PITCH  = 80;               // 64B data + 16B pad
    constexpr uint32_t OFF_B  = 256u * PITCH;     // 20480
    constexpr uint32_t STAGE  = OFF_B + 128u * PITCH;  // 30720

    extern __shared__ char sdyn[];
    __shared__ float sm_s[4][256], sm_q[4][256];
    __shared__ float2 sscf[128], sbbf[128];       // fp32 per-channel-pair scale/bias

    const int tid  = threadIdx.x;
    const int lane = tid & 31, wid = tid >> 5;
    const int mw   = wid & 3;        // M block of 64
    const int nw   = wid >> 2;       // N block of 32
    const int b    = blockIdx.y;
    const int n0   = blockIdx.x * 128;
    const size_t bn0 = (size_t)b * N_ + n0;
    const uint32_t sb0 = smem_u32(sdyn);

    if (FUSE && tid < 128) {
        sscf[tid] = make_float2(sbn[2 * tid], sbn[2 * tid + 1]);
        sbbf[tid] = make_float2(sbn[256 + 2 * tid], sbn[256 + 2 * tid + 1]);
    }

    auto load_stage = [&](int kt, int buf) {
        uint32_t base = sb0 + (uint32_t)buf * STAGE;
        #pragma unroll
        for (int i = 0; i < 2; i++) {              // A: 256 rows x 4 chunks
            int c = tid + i * 512;
            int row = (c >> 2) & 255, ch = c & 3;
            const __half* src = Aq + (size_t)row * KDIM + kt + ch * 8;
            cpa16(base + (uint32_t)row * PITCH + ch * 16, src);
        }
        {                                           // B: 128 rows x 4 chunks
            int row = (tid >> 2) & 127, ch = tid & 3;
            const __half* src = Bq + (bn0 + row) * KDIM + kt + ch * 8;
            cpa16(base + OFF_B + (uint32_t)row * PITCH + ch * 16, src);
        }
        CP_COMMIT();
    };

    float acc[4][4][4] = {};

    load_stage(0, 0);

    #pragma unroll 1
    for (int s = 0; s < NS; s++) {
        if (s + 1 < NS) { load_stage((s + 1) * 32, (s + 1) & 1); CP_WAIT1(); }
        else            { CP_WAIT0(); }
        __syncthreads();

        uint32_t base = sb0 + (uint32_t)(s & 1) * STAGE;
        #pragma unroll
        for (int ks = 0; ks < 2; ks++) {
            uint32_t a[4][4];
            #pragma unroll
            for (int mt = 0; mt < 4; mt++) {
                uint32_t row = (uint32_t)(mw * 64 + mt * 16 + (lane & 15));
                ldsm4(base + row * PITCH + ks * 32 + ((lane >> 4) << 4), a[mt]);
            }
            // fp32 per-k scale/bias for this thread's B fragment positions
            float2 scA, scB, bsA, bsB;
            if (FUSE) {
                int kp = s * 16 + ks * 8 + (lane & 3);
                scA = sscf[kp];     bsA = sbbf[kp];
                scB = sscf[kp + 4]; bsB = sbbf[kp + 4];
            }
            #pragma unroll
            for (int pair = 0; pair < 2; pair++) {
                uint32_t rowB = (uint32_t)(nw * 32 + pair * 16
                               + ((lane >> 4) << 3) + (lane & 7));
                uint32_t bfr[4];
                ldsm4(base + OFF_B + rowB * PITCH
                      + ks * 32 + (((lane >> 3) & 1) << 4), bfr);
                if (FUSE) {
                    #pragma unroll
                    for (int j = 0; j < 4; j++) {
                        const float2 sc = (j & 1) ? scB : scA;
                        const float2 bs = (j & 1) ? bsB : bsA;
                        float2 v = __half22float2(*(__half2*)&bfr[j]);
                        v.x = fmaxf(fmaf(v.x, sc.x, bs.x), 0.0f);
                        v.y = fmaxf(fmaf(v.y, sc.y, bs.y), 0.0f);
                        *(__half2*)&bfr[j] = __floats2half2_rn(v.x, v.y);
                    }
                }
                #pragma unroll
                for (int h = 0; h < 2; h++) {
                    int nt = pair * 2 + h;
                    #pragma unroll
                    for (int mt = 0; mt < 4; mt++)
                        mma16816(acc[mt][nt], a[mt], &bfr[h * 2]);
                }
            }
        }
        __syncthreads();
    }

    // ---- epilogue: bias, BN partials, smem-staged fp16 coalesced flush -------
    float* sy = (float*)sdyn;             // [64][260] per N-half
    const int r = lane >> 2;
    float csum[8] = {}, cssq[8] = {};

    #pragma unroll
    for (int half = 0; half < 2; half++) {
        if ((nw >> 1) == half) {
            #pragma unroll
            for (int mt = 0; mt < 4; mt++) {
                const int m0 = mw * 64 + mt * 16 + r;
                const int m1 = m0 + 8;
                const float bv0 = bias[m0], bv1 = bias[m1];
                #pragma unroll
                for (int nt = 0; nt < 4; nt++) {
                    float* c = acc[mt][nt];
                    int nl = (nw & 1) * 32 + nt * 8 + (lane & 3) * 2;
                    float v0 = c[0] + bv0, v1 = c[1] + bv0;
                    float v2 = c[2] + bv1, v3 = c[3] + bv1;
                    sy[nl * 260 + m0]       = v0;
                    sy[(nl + 1) * 260 + m0] = v1;
                    sy[nl * 260 + m1]       = v2;
                    sy[(nl + 1) * 260 + m1] = v3;
                    csum[mt * 2]     += v0 + v1;
                    cssq[mt * 2]     += fmaf(v0, v0, v1 * v1);
                    csum[mt * 2 + 1] += v2 + v3;
                    cssq[mt * 2 + 1] += fmaf(v2, v2, v3 * v3);
                }
            }
        }
        __syncthreads();
        // coalesced fp16 flush: 64 rows x 512B, four rows per iteration
        #pragma unroll 4
        for (int i = 0; i < 16; i++) {
            int row = i * 4 + (tid >> 7);
            int c2  = tid & 127;
            __half2 hp = __floats2half2_rn(sy[row * 260 + c2 * 2],
                                           sy[row * 260 + c2 * 2 + 1]);
            *(__half2*)(Y + (bn0 + half * 64 + row) * 256 + c2 * 2) = hp;
        }
        __syncthreads();
    }

    // BN partials
    #pragma unroll
    for (int j = 0; j < 8; j++) {
        csum[j] += __shfl_xor_sync(0xffffffffu, csum[j], 1);
        csum[j] += __shfl_xor_sync(0xffffffffu, csum[j], 2);
        cssq[j] += __shfl_xor_sync(0xffffffffu, cssq[j], 1);
        cssq[j] += __shfl_xor_sync(0xffffffffu, cssq[j], 2);
    }
    if ((lane & 3) == 0) {
        #pragma unroll
        for (int mt = 0; mt < 4; mt++) {
            #pragma unroll
            for (int h = 0; h < 2; h++) {
                int ch = mw * 64 + mt * 16 + r + h * 8;
                sm_s[nw][ch] = csum[mt * 2 + h];
                sm_q[nw][ch] = cssq[mt * 2 + h];
            }
        }
    }
    __syncthreads();
    if (tid < 256) {
        int cta = blockIdx.x + blockIdx.y * gridDim.x;
        psum[tid * 1024 + cta] = sm_s[0][tid] + sm_s[1][tid] + sm_s[2][tid] + sm_s[3][tid];
        pssq[tid * 1024 + cta] = sm_q[0][tid] + sm_q[1][tid] + sm_q[2][tid] + sm_q[3][tid];
    }
}

// ---------------- BN fold: reduce 1024 partials per channel -------------------
__global__ __launch_bounds__(256) void stats2_kernel(
    const float* __restrict__ g, const float* __restrict__ beta,
    float* __restrict__ sb)
{
    const int o = blockIdx.x;
    const int t = threadIdx.x;
    float s = 0.0f, ss = 0.0f;
    #pragma unroll
    for (int i = 0; i < 4; i++) {
        s  += g_psum[o * 1024 + t * 4 + i];
        ss += g_pssq[o * 1024 + t * 4 + i];
    }
    const int lane = t & 31, w = t >> 5;
    #pragma unroll
    for (int off = 16; off; off >>= 1) {
        s  += __shfl_down_sync(0xffffffffu, s,  off);
        ss += __shfl_down_sync(0xffffffffu, ss, off);
    }
    __shared__ float rs[8], rss[8];
    if (lane == 0) { rs[w] = s; rss[w] = ss; }
    __syncthreads();
    if (t == 0) {
        float ts = 0.0f, tss = 0.0f;
        #pragma unroll
        for (int i = 0; i < 8; i++) { ts += rs[i]; tss += rss[i]; }
        float mean = ts * CNT_INV;
        float var  = tss * CNT_INV - mean * mean;
        float rstd = rsqrtf(var + BN_EPS);
        float sc = g[o] * rstd;
        sb[o]       = sc;
        sb[256 + o] = beta[o] - mean * sc;
    }
}

// ---------------- final norm + relu + transpose -> out [B][256][N] ------------
// Tile: 32 n-rows x 64 m. half2 loads (128B rows), fp32 writes (128B rows).
__global__ __launch_bounds__(256) void outt_kernel(
    const __half* __restrict__ y, const float* __restrict__ sb,
    float* __restrict__ out)
{
    __shared__ float tile[32][65];
    const int b  = blockIdx.z;
    const int n0 = blockIdx.x * 32;
    const int m0 = blockIdx.y * 64;
    const int tx = threadIdx.x;      // 0..31
    const int ty = threadIdx.y;      // 0..7
    #pragma unroll
    for (int r = 0; r < 4; r++) {
        int n = n0 + ty + r * 8;
        __half2 hv = *(const __half2*)(y + ((size_t)b * N_ + n) * 256 + m0 + tx * 2);
        float2 f = __half22float2(hv);
        tile[ty + r * 8][tx * 2]     = f.x;
        tile[ty + r * 8][tx * 2 + 1] = f.y;
    }
    __syncthreads();
    #pragma unroll
    for (int r = 0; r < 8; r++) {
        int m = m0 + ty + r * 8;
        float sc = sb[m], bs = sb[256 + m];
        out[((size_t)b * 256 + m) * N_ + n0 + tx] =
            fmaxf(fmaf(tile[tx][ty + r * 8], sc, bs), 0.0f);
    }
}

// ---------------- launcher ----------------------------------------------------
extern "C" void kernel_launch(void* const* d_in, const int* in_sizes, int n_in,
                              void* d_out, int out_size)
{
    const float* xyz1 = (const float*)d_in[0];
    const float* xyz2 = (const float*)d_in[1];
    const float* pts1 = (const float*)d_in[2];
    const float* pts2 = (const float*)d_in[3];
    const float* W0   = (const float*)d_in[4];
    const float* b0   = (const float*)d_in[5];
    const float* gg0  = (const float*)d_in[6];
    const float* be0  = (const float*)d_in[7];
    const float* W1   = (const float*)d_in[8];
    const float* b1   = (const float*)d_in[9];
    const float* gg1  = (const float*)d_in[10];
    const float* be1  = (const float*)d_in[11];
    float* out = (float*)d_out;

    __half *xq, *w0q, *w1q, *y;
    float *psum, *pssq, *sb1, *sb2;
    cudaGetSymbolAddress((void**)&xq,  g_xq);
    cudaGetSymbolAddress((void**)&w0q, g_w0q);
    cudaGetSymbolAddress((void**)&w1q, g_w1q);
    cudaGetSymbolAddress((void**)&y,   g_y);
    cudaGetSymbolAddress((void**)&psum, g_psum);
    cudaGetSymbolAddress((void**)&pssq, g_pssq);
    cudaGetSymbolAddress((void**)&sb1, g_sb1);
    cudaGetSymbolAddress((void**)&sb2, g_sb2);

    const int GEMM_SMEM = 68096;   // max(2 stages 61440, sy 64*260*4=66560) +pad
    cudaFuncSetAttribute(gemm_mma<K1_, false>, cudaFuncAttributeMaxDynamicSharedMemorySize, GEMM_SMEM);
    cudaFuncSetAttribute(gemm_mma<O_,  true >, cudaFuncAttributeMaxDynamicSharedMemorySize, GEMM_SMEM);

    // prep
    wconv_kernel<<<(O_ * K1_ + 255) / 256, 256>>>(W0, w0q, O_ * K1_);
    wconv_kernel<<<(O_ * O_  + 255) / 256, 256>>>(W1, w1q, O_ * O_);
    knn_kernel<<<dim3(N_ / 512, B_), 256>>>(xyz1, xyz2);
    transpose_p2_kernel<<<dim3(S_ / 32, C2_ / 32, B_), dim3(32, 8)>>>(pts2);
    gather_kernel<<<dim3(N_ / 32, B_), 256>>>();
    p1t_kernel<<<dim3(N_ / 32, C1_ / 32, B_), dim3(32, 8)>>>(pts1);

    // layer 1 -> y1
    gemm_mma<K1_, false><<<dim3(N_ / 128, B_), 512, GEMM_SMEM>>>(
        w0q, xq, b0, y, psum, pssq, nullptr);
    stats2_kernel<<<256, 256>>>(gg0, be0, sb1);

    // layer 2: reads raw y1, fp32 norm+relu on B fragments, writes y2 in place
    gemm_mma<O_, true><<<dim3(N_ / 128, B_), 512, GEMM_SMEM>>>(
        w1q, y, b1, y, psum, pssq, sb1);
    stats2_kernel<<<256, 256>>>(gg1, be1, sb2);

    // output
    outt_kernel<<<dim3(N_ / 32, 4, B_), dim3(32, 8)>>>(y, sb2, out);
}

// round 16
// speedup vs baseline: 2.1966x; 1.0619x over previous
#include <cuda_runtime.h>
#include <cuda_fp16.h>
#include <cstdint>

static constexpr int B_  = 8;
static constexpr int N_  = 16384;
static constexpr int S_  = 2048;
static constexpr int C1_ = 128;
static constexpr int C2_ = 256;
static constexpr int K1_ = 384;
static constexpr int O_  = 256;
static constexpr float BN_EPS  = 1e-5f;
static constexpr float CNT_INV = 1.0f / (float)(B_ * N_);

// ---------------- device-global scratch (no cudaMalloc allowed) ---------------
__device__ __half g_xq[(size_t)B_ * N_ * K1_];   // concat input, fp16 [n][k]
__device__ __half g_y [(size_t)B_ * N_ * O_];    // y1, fp16 (n-major)
__device__ __half g_y2[(size_t)B_ * N_ * O_];    // y2, fp16 (n-major)
__device__ float  g_p2t[(size_t)B_ * S_ * C2_];  // points2 transposed [B][S][C]
__device__ int    g_idx[(size_t)B_ * N_ * 3];
__device__ float  g_w  [(size_t)B_ * N_ * 3];
__device__ __half g_w0q[O_ * K1_];               // W0 fp16
__device__ __half g_w1q[O_ * O_];                // W1 fp16
__device__ float  g_psum[256 * 1024], g_pssq[256 * 1024];
__device__ float  g_sb1[512], g_sb2[512];

// ---------------- small PTX helpers ------------------------------------------
__device__ __forceinline__ uint32_t smem_u32(const void* p) {
    uint32_t a;
    asm("{ .reg .u64 t; cvta.to.shared.u64 t, %1; cvt.u32.u64 %0, t; }"
        : "=r"(a) : "l"(p));
    return a;
}
__device__ __forceinline__ void cpa16(uint32_t dst, const void* src) {
    asm volatile("cp.async.cg.shared.global [%0], [%1], 16;"
                 :: "r"(dst), "l"(src) : "memory");
}
#define CP_COMMIT() asm volatile("cp.async.commit_group;" ::: "memory")
#define CP_WAIT0()  asm volatile("cp.async.wait_group 0;" ::: "memory")
#define CP_WAIT1()  asm volatile("cp.async.wait_group 1;" ::: "memory")

__device__ __forceinline__ void ldsm4(uint32_t addr, uint32_t* r) {
    asm volatile("ldmatrix.sync.aligned.m8n8.x4.shared.b16 {%0,%1,%2,%3}, [%4];"
                 : "=r"(r[0]), "=r"(r[1]), "=r"(r[2]), "=r"(r[3]) : "r"(addr));
}
__device__ __forceinline__ void mma16816(float* c, const uint32_t* a, const uint32_t* b) {
    asm volatile(
        "mma.sync.aligned.m16n8k16.row.col.f32.f16.f16.f32 "
        "{%0,%1,%2,%3}, {%4,%5,%6,%7}, {%8,%9}, {%0,%1,%2,%3};"
        : "+f"(c[0]), "+f"(c[1]), "+f"(c[2]), "+f"(c[3])
        : "r"(a[0]), "r"(a[1]), "r"(a[2]), "r"(a[3]), "r"(b[0]), "r"(b[1]));
}

// ---------------- kNN (2 queries per thread, exact squared distances) ---------
__global__ __launch_bounds__(256) void knn_kernel(
    const float* __restrict__ xyz1, const float* __restrict__ xyz2)
{
    __shared__ float4 sp[S_];
    const int b = blockIdx.y;
    const int t = threadIdx.x;
    for (int s = t; s < S_; s += 256) {
        const float* p = xyz2 + ((size_t)b * S_ + s) * 3;
        sp[s] = make_float4(p[0], p[1], p[2], 0.0f);
    }
    __syncthreads();

    const int nb = blockIdx.x * 512 + t;
    float qx[2], qy[2], qz[2];
    float d0[2], d1[2], d2[2];
    int   i0[2], i1[2], i2[2];
    #pragma unroll
    for (int j = 0; j < 2; j++) {
        const float* q = xyz1 + ((size_t)b * N_ + nb + j * 256) * 3;
        qx[j] = q[0]; qy[j] = q[1]; qz[j] = q[2];
        d0[j] = 3.4e38f; d1[j] = 3.4e38f; d2[j] = 3.4e38f;
        i0[j] = 0; i1[j] = 0; i2[j] = 0;
    }
    #pragma unroll 4
    for (int s = 0; s < S_; s++) {
        float4 p = sp[s];
        #pragma unroll
        for (int j = 0; j < 2; j++) {
            float dx = qx[j] - p.x, dy = qy[j] - p.y, dz = qz[j] - p.z;
            float d = fmaf(dz, dz, fmaf(dy, dy, dx * dx));
            if (d < d2[j]) {
                if (d < d1[j]) {
                    d2[j] = d1[j]; i2[j] = i1[j];
                    if (d < d0[j]) { d1[j] = d0[j]; i1[j] = i0[j]; d0[j] = d; i0[j] = s; }
                    else           { d1[j] = d;  i1[j] = s; }
                } else { d2[j] = d; i2[j] = s; }
            }
        }
    }
    #pragma unroll
    for (int j = 0; j < 2; j++) {
        float a = fmaxf(d0[j], 1e-10f), bb = fmaxf(d1[j], 1e-10f), c = fmaxf(d2[j], 1e-10f);
        float w0 = 1.0f / a, w1 = 1.0f / bb, w2 = 1.0f / c;
        float sw = w0 + w1 + w2;
        size_t base = ((size_t)b * N_ + nb + j * 256) * 3;
        g_idx[base] = i0[j]; g_idx[base + 1] = i1[j]; g_idx[base + 2] = i2[j];
        g_w[base] = w0 / sw; g_w[base + 1] = w1 / sw; g_w[base + 2] = w2 / sw;
    }
}

// ---------------- transpose points2 [B][C][S] -> [B][S][C] --------------------
__global__ void transpose_p2_kernel(const float* __restrict__ p2)
{
    __shared__ float tile[32][33];
    const int b  = blockIdx.z;
    const int s0 = blockIdx.x * 32;
    const int c0 = blockIdx.y * 32;
    #pragma unroll
    for (int r = 0; r < 4; r++) {
        int c = c0 + threadIdx.y + r * 8;
        tile[threadIdx.y + r * 8][threadIdx.x] =
            p2[((size_t)b * C2_ + c) * S_ + s0 + threadIdx.x];
    }
    __syncthreads();
    #pragma unroll
    for (int r = 0; r < 4; r++) {
        int s = s0 + threadIdx.y + r * 8;
        g_p2t[((size_t)b * S_ + s) * C2_ + c0 + threadIdx.x] =
            tile[threadIdx.x][threadIdx.y + r * 8];
    }
}

// ---------------- gather + weighted sum -> xcat channels [0,256) --------------
// 256 thr = 128 channel-pairs x 2 n-points; float2 reads, half2 writes.
__global__ __launch_bounds__(256) void gather_kernel()
{
    const int b  = blockIdx.y;
    const int n0 = blockIdx.x * 32;
    const int cp = threadIdx.x & 127;    // channel pair
    const int no = threadIdx.x >> 7;     // n offset 0/1
    #pragma unroll 2
    for (int it = 0; it < 16; it++) {
        int nl = it * 2 + no;
        size_t base = ((size_t)b * N_ + n0 + nl) * 3;
        int i0 = g_idx[base], i1 = g_idx[base + 1], i2 = g_idx[base + 2];
        float w0 = g_w[base], w1 = g_w[base + 1], w2 = g_w[base + 2];
        const float2* r0 = (const float2*)(g_p2t + ((size_t)b * S_ + i0) * C2_);
        const float2* r1 = (const float2*)(g_p2t + ((size_t)b * S_ + i1) * C2_);
        const float2* r2 = (const float2*)(g_p2t + ((size_t)b * S_ + i2) * C2_);
        float2 a0 = r0[cp], a1 = r1[cp], a2 = r2[cp];
        float v0 = fmaf(w2, a2.x, fmaf(w1, a1.x, w0 * a0.x));
        float v1 = fmaf(w2, a2.y, fmaf(w1, a1.y, w0 * a0.y));
        *(__half2*)(g_xq + ((size_t)b * N_ + n0 + nl) * K1_ + cp * 2) =
            __floats2half2_rn(v0, v1);
    }
}

// ---------------- points1 transpose -> xcat channels [256,384) ----------------
__global__ void p1t_kernel(const float* __restrict__ p1)
{
    __shared__ float tile[32][33];
    const int b  = blockIdx.z;
    const int n0 = blockIdx.x * 32;
    const int c0 = blockIdx.y * 32;
    #pragma unroll
    for (int r = 0; r < 4; r++) {
        int c = c0 + threadIdx.y + r * 8;
        tile[threadIdx.y + r * 8][threadIdx.x] =
            p1[((size_t)b * C1_ + c) * N_ + n0 + threadIdx.x];
    }
    __syncthreads();
    #pragma unroll
    for (int r = 0; r < 4; r++) {
        int n = n0 + threadIdx.y + r * 8;
        float v = tile[threadIdx.x][threadIdx.y + r * 8];
        g_xq[((size_t)b * N_ + n) * K1_ + 256 + c0 + threadIdx.x] = __float2half_rn(v);
    }
}

// ---------------- weight fp16 convert -----------------------------------------
__global__ void wconv_kernel(const float* __restrict__ w,
                             __half* __restrict__ q, int n)
{
    int i = blockIdx.x * 256 + threadIdx.x;
    if (i < n) q[i] = __float2half_rn(w[i]);
}

// ---------------- mma.sync fp16 GEMM (CTA tile 128x128, 2 CTAs/SM) ------------
// FUSE=0: D = W @ X             (layer 1; X = g_xq)
// FUSE=1: D = W @ relu(sc*X+bs) (layer 2; X = y1; affine in fp32 on B frags)
// CTA: 256 thr = 8 warps (2 in M x 4 in N). Warp tile 64x32.
// Epilogue: BN partials from fp32 accs; y stored fp16 via smem-staged flush.
template<int KDIM, bool FUSE>
__global__ __launch_bounds__(256, 2) void gemm_mma(
    const __half* __restrict__ Aq, const __half* __restrict__ Bq,
    const float* __restrict__ bias, __half* __restrict__ Y,
    float* __restrict__ psum, float* __restrict__ pssq,
    const float* __restrict__ sbn)
{
    constexpr int NS = KDIM / 32;                 // K stages of 32
    constexpr uint32_t PITCH  = 80;               // 64B data + 16B pad
    constexpr uint32_t OFF_B  = 128u * PITCH;     // 10240
    constexpr uint32_t STAGE  = OFF_B + 128u * PITCH;  // 20480

    extern __shared__ char sdyn[];
    __shared__ float sm_s[4][128], sm_q[4][128];
    __shared__ float2 sscf[128], sbbf[128];       // fp32 per-channel-pair scale/bias

    const int tid  = threadIdx.x;
    const int lane = tid & 31, wid = tid >> 5;
    const int mw   = wid & 1;        // M block of 64
    const int nw   = wid >> 1;       // N block of 32
    const int b    = blockIdx.z;
    const int mt0  = blockIdx.y * 128;
    const int n0   = blockIdx.x * 128;
    const size_t bn0 = (size_t)b * N_ + n0;
    const uint32_t sb0 = smem_u32(sdyn);

    if (FUSE && tid < 128) {
        sscf[tid] = make_float2(sbn[2 * tid], sbn[2 * tid + 1]);
        sbbf[tid] = make_float2(sbn[256 + 2 * tid], sbn[256 + 2 * tid + 1]);
    }

    auto load_stage = [&](int kt, int buf) {
        uint32_t base = sb0 + (uint32_t)buf * STAGE;
        #pragma unroll
        for (int i = 0; i < 2; i++) {              // A: 128 rows x 4 chunks
            int c = tid + i * 256;
            int row = (c >> 2) & 127, ch = c & 3;
            const __half* src = Aq + (size_t)(mt0 + row) * KDIM + kt + ch * 8;
            cpa16(base + (uint32_t)row * PITCH + ch * 16, src);
        }
        #pragma unroll
        for (int i = 0; i < 2; i++) {              // B: 128 rows x 4 chunks
            int c = tid + i * 256;
            int row = (c >> 2) & 127, ch = c & 3;
            const __half* src = Bq + (bn0 + row) * KDIM + kt + ch * 8;
            cpa16(base + OFF_B + (uint32_t)row * PITCH + ch * 16, src);
        }
        CP_COMMIT();
    };

    float acc[4][4][4] = {};

    load_stage(0, 0);

    #pragma unroll 1
    for (int s = 0; s < NS; s++) {
        if (s + 1 < NS) { load_stage((s + 1) * 32, (s + 1) & 1); CP_WAIT1(); }
        else            { CP_WAIT0(); }
        __syncthreads();

        uint32_t base = sb0 + (uint32_t)(s & 1) * STAGE;
        #pragma unroll
        for (int ks = 0; ks < 2; ks++) {
            uint32_t a[4][4];
            #pragma unroll
            for (int mt = 0; mt < 4; mt++) {
                uint32_t row = (uint32_t)(mw * 64 + mt * 16 + (lane & 15));
                ldsm4(base + row * PITCH + ks * 32 + ((lane >> 4) << 4), a[mt]);
            }
            // fp32 per-k scale/bias for this thread's B fragment positions
            float2 scA, scB, bsA, bsB;
            if (FUSE) {
                int kp = s * 16 + ks * 8 + (lane & 3);
                scA = sscf[kp];     bsA = sbbf[kp];
                scB = sscf[kp + 4]; bsB = sbbf[kp + 4];
            }
            #pragma unroll
            for (int pair = 0; pair < 2; pair++) {
                uint32_t rowB = (uint32_t)(nw * 32 + pair * 16
                               + ((lane >> 4) << 3) + (lane & 7));
                uint32_t bfr[4];
                ldsm4(base + OFF_B + rowB * PITCH
                      + ks * 32 + (((lane >> 3) & 1) << 4), bfr);
                if (FUSE) {
                    #pragma unroll
                    for (int j = 0; j < 4; j++) {
                        const float2 sc = (j & 1) ? scB : scA;
                        const float2 bs = (j & 1) ? bsB : bsA;
                        float2 v = __half22float2(*(__half2*)&bfr[j]);
                        v.x = fmaxf(fmaf(v.x, sc.x, bs.x), 0.0f);
                        v.y = fmaxf(fmaf(v.y, sc.y, bs.y), 0.0f);
                        *(__half2*)&bfr[j] = __floats2half2_rn(v.x, v.y);
                    }
                }
                #pragma unroll
                for (int h = 0; h < 2; h++) {
                    int nt = pair * 2 + h;
                    #pragma unroll
                    for (int mt = 0; mt < 4; mt++)
                        mma16816(acc[mt][nt], a[mt], &bfr[h * 2]);
                }
            }
        }
        __syncthreads();
    }

    // ---- epilogue: bias, BN partials, smem-staged fp16 coalesced flush -------
    float* sy = (float*)sdyn;             // [64][132] per N-half
    const int r = lane >> 2;
    float csum[8] = {}, cssq[8] = {};

    #pragma unroll
    for (int half = 0; half < 2; half++) {
        if ((nw >> 1) == half) {
            #pragma unroll
            for (int mt = 0; mt < 4; mt++) {
                const int m0 = mw * 64 + mt * 16 + r;
                const int m1 = m0 + 8;
                const float bv0 = bias[mt0 + m0], bv1 = bias[mt0 + m1];
                #pragma unroll
                for (int nt = 0; nt < 4; nt++) {
                    float* c = acc[mt][nt];
                    int nl = (nw & 1) * 32 + nt * 8 + (lane & 3) * 2;
                    float v0 = c[0] + bv0, v1 = c[1] + bv0;
                    float v2 = c[2] + bv1, v3 = c[3] + bv1;
                    sy[nl * 132 + m0]       = v0;
                    sy[(nl + 1) * 132 + m0] = v1;
                    sy[nl * 132 + m1]       = v2;
                    sy[(nl + 1) * 132 + m1] = v3;
                    csum[mt * 2]     += v0 + v1;
                    cssq[mt * 2]     += fmaf(v0, v0, v1 * v1);
                    csum[mt * 2 + 1] += v2 + v3;
                    cssq[mt * 2 + 1] += fmaf(v2, v2, v3 * v3);
                }
            }
        }
        __syncthreads();
        // coalesced fp16 flush: 64 rows x 256B, four rows per iteration
        #pragma unroll 4
        for (int i = 0; i < 16; i++) {
            int row = i * 4 + (tid >> 6);
            int c2  = tid & 63;
            __half2 hp = __floats2half2_rn(sy[row * 132 + c2 * 2],
                                           sy[row * 132 + c2 * 2 + 1]);
            *(__half2*)(Y + (bn0 + half * 64 + row) * 256 + mt0 + c2 * 2) = hp;
        }
        __syncthreads();
    }

    // BN partials
    #pragma unroll
    for (int j = 0; j < 8; j++) {
        csum[j] += __shfl_xor_sync(0xffffffffu, csum[j], 1);
        csum[j] += __shfl_xor_sync(0xffffffffu, csum[j], 2);
        cssq[j] += __shfl_xor_sync(0xffffffffu, cssq[j], 1);
        cssq[j] += __shfl_xor_sync(0xffffffffu, cssq[j], 2);
    }
    if ((lane & 3) == 0) {
        #pragma unroll
        for (int mt = 0; mt < 4; mt++) {
            #pragma unroll
            for (int h = 0; h < 2; h++) {
                int ch = mw * 64 + mt * 16 + r + h * 8;
                sm_s[nw][ch] = csum[mt * 2 + h];
                sm_q[nw][ch] = cssq[mt * 2 + h];
            }
        }
    }
    __syncthreads();
    if (tid < 128) {
        int cta = blockIdx.x + blockIdx.z * gridDim.x;
        psum[(mt0 + tid) * 1024 + cta] =
            sm_s[0][tid] + sm_s[1][tid] + sm_s[2][tid] + sm_s[3][tid];
        pssq[(mt0 + tid) * 1024 + cta] =
            sm_q[0][tid] + sm_q[1][tid] + sm_q[2][tid] + sm_q[3][tid];
    }
}

// ---------------- BN fold: reduce 1024 partials per channel -------------------
__global__ __launch_bounds__(256) void stats2_kernel(
    const float* __restrict__ g, const float* __restrict__ beta,
    float* __restrict__ sb)
{
    const int o = blockIdx.x;
    const int t = threadIdx.x;
    float s = 0.0f, ss = 0.0f;
    #pragma unroll
    for (int i = 0; i < 4; i++) {
        s  += g_psum[o * 1024 + t * 4 + i];
        ss += g_pssq[o * 1024 + t * 4 + i];
    }
    const int lane = t & 31, w = t >> 5;
    #pragma unroll
    for (int off = 16; off; off >>= 1) {
        s  += __shfl_down_sync(0xffffffffu, s,  off);
        ss += __shfl_down_sync(0xffffffffu, ss, off);
    }
    __shared__ float rs[8], rss[8];
    if (lane == 0) { rs[w] = s; rss[w] = ss; }
    __syncthreads();
    if (t == 0) {
        float ts = 0.0f, tss = 0.0f;
        #pragma unroll
        for (int i = 0; i < 8; i++) { ts += rs[i]; tss += rss[i]; }
        float mean = ts * CNT_INV;
        float var  = tss * CNT_INV - mean * mean;
        float rstd = rsqrtf(var + BN_EPS);
        float sc = g[o] * rstd;
        sb[o]       = sc;
        sb[256 + o] = beta[o] - mean * sc;
    }
}

// ---------------- final norm + relu + transpose -> out [B][256][N] ------------
// Tile: 32 n-rows x 64 m. half2 loads (128B rows), fp32 writes (128B rows).
__global__ __launch_bounds__(256) void outt_kernel(
    const __half* __restrict__ y, const float* __restrict__ sb,
    float* __restrict__ out)
{
    __shared__ float tile[32][65];
    const int b  = blockIdx.z;
    const int n0 = blockIdx.x * 32;
    const int m0 = blockIdx.y * 64;
    const int tx = threadIdx.x;      // 0..31
    const int ty = threadIdx.y;      // 0..7
    #pragma unroll
    for (int r = 0; r < 4; r++) {
        int n = n0 + ty + r * 8;
        __half2 hv = *(const __half2*)(y + ((size_t)b * N_ + n) * 256 + m0 + tx * 2);
        float2 f = __half22float2(hv);
        tile[ty + r * 8][tx * 2]     = f.x;
        tile[ty + r * 8][tx * 2 + 1] = f.y;
    }
    __syncthreads();
    #pragma unroll
    for (int r = 0; r < 8; r++) {
        int m = m0 + ty + r * 8;
        float sc = sb[m], bs = sb[256 + m];
        out[((size_t)b * 256 + m) * N_ + n0 + tx] =
            fmaxf(fmaf(tile[tx][ty + r * 8], sc, bs), 0.0f);
    }
}

// ---------------- launcher ----------------------------------------------------
extern "C" void kernel_launch(void* const* d_in, const int* in_sizes, int n_in,
                              void* d_out, int out_size)
{
    const float* xyz1 = (const float*)d_in[0];
    const float* xyz2 = (const float*)d_in[1];
    const float* pts1 = (const float*)d_in[2];
    const float* pts2 = (const float*)d_in[3];
    const float* W0   = (const float*)d_in[4];
    const float* b0   = (const float*)d_in[5];
    const float* gg0  = (const float*)d_in[6];
    const float* be0  = (const float*)d_in[7];
    const float* W1   = (const float*)d_in[8];
    const float* b1   = (const float*)d_in[9];
    const float* gg1  = (const float*)d_in[10];
    const float* be1  = (const float*)d_in[11];
    float* out = (float*)d_out;

    __half *xq, *w0q, *w1q, *y, *y2;
    float *psum, *pssq, *sb1, *sb2;
    cudaGetSymbolAddress((void**)&xq,  g_xq);
    cudaGetSymbolAddress((void**)&w0q, g_w0q);
    cudaGetSymbolAddress((void**)&w1q, g_w1q);
    cudaGetSymbolAddress((void**)&y,   g_y);
    cudaGetSymbolAddress((void**)&y2,  g_y2);
    cudaGetSymbolAddress((void**)&psum, g_psum);
    cudaGetSymbolAddress((void**)&pssq, g_pssq);
    cudaGetSymbolAddress((void**)&sb1, g_sb1);
    cudaGetSymbolAddress((void**)&sb2, g_sb2);

    const int GEMM_SMEM = 40960;   // max(2 stages 40960, sy 64*132*4=33792)
    cudaFuncSetAttribute(gemm_mma<K1_, false>, cudaFuncAttributeMaxDynamicSharedMemorySize, GEMM_SMEM);
    cudaFuncSetAttribute(gemm_mma<O_,  true >, cudaFuncAttributeMaxDynamicSharedMemorySize, GEMM_SMEM);

    // prep
    wconv_kernel<<<(O_ * K1_ + 255) / 256, 256>>>(W0, w0q, O_ * K1_);
    wconv_kernel<<<(O_ * O_  + 255) / 256, 256>>>(W1, w1q, O_ * O_);
    knn_kernel<<<dim3(N_ / 512, B_), 256>>>(xyz1, xyz2);
    transpose_p2_kernel<<<dim3(S_ / 32, C2_ / 32, B_), dim3(32, 8)>>>(pts2);
    gather_kernel<<<dim3(N_ / 32, B_), 256>>>();
    p1t_kernel<<<dim3(N_ / 32, C1_ / 32, B_), dim3(32, 8)>>>(pts1);

    // layer 1 -> y1
    gemm_mma<K1_, false><<<dim3(N_ / 128, 2, B_), 256, GEMM_SMEM>>>(
        w0q, xq, b0, y, psum, pssq, nullptr);
    stats2_kernel<<<256, 256>>>(gg0, be0, sb1);

    // layer 2: reads y1, fp32 norm+relu on B fragments, writes y2
    gemm_mma<O_, true><<<dim3(N_ / 128, 2, B_), 256, GEMM_SMEM>>>(
        w1q, y, b1, y2, psum, pssq, sb1);
    stats2_kernel<<<256, 256>>>(gg1, be1, sb2);

    // output
    outt_kernel<<<dim3(N_ / 32, 4, B_), dim3(32, 8)>>>(y2, sb2, out);
}

// round 17
// speedup vs baseline: 2.2752x; 1.0358x over previous
#include <cuda_runtime.h>
#include <cuda_fp16.h>
#include <cstdint>

static constexpr int B_  = 8;
static constexpr int N_  = 16384;
static constexpr int S_  = 2048;
static constexpr int C1_ = 128;
static constexpr int C2_ = 256;
static constexpr int K1_ = 384;
static constexpr int O_  = 256;
static constexpr float BN_EPS  = 1e-5f;
static constexpr float CNT_INV = 1.0f / (float)(B_ * N_);

// ---------------- device-global scratch (no cudaMalloc allowed) ---------------
__device__ __half g_xq[(size_t)B_ * N_ * K1_];   // concat input, fp16 [n][k]
__device__ __half g_y [(size_t)B_ * N_ * O_];    // y1, fp16 (n-major)
__device__ __half g_y2[(size_t)B_ * N_ * O_];    // y2, fp16 (n-major)
__device__ float  g_p2t[(size_t)B_ * S_ * C2_];  // points2 transposed [B][S][C]
__device__ float  g_kd [(size_t)B_ * N_ * 6];    // per-half top-3 distances
__device__ int    g_ki [(size_t)B_ * N_ * 6];    // per-half top-3 indices
__device__ int    g_idx[(size_t)B_ * N_ * 3];
__device__ float  g_w  [(size_t)B_ * N_ * 3];
__device__ __half g_w0q[O_ * K1_];               // W0 fp16
__device__ __half g_w1q[O_ * O_];                // W1 fp16
__device__ float  g_psum[256 * 1024], g_pssq[256 * 1024];
__device__ float  g_sb1[512], g_sb2[512];

// ---------------- small PTX helpers ------------------------------------------
__device__ __forceinline__ uint32_t smem_u32(const void* p) {
    uint32_t a;
    asm("{ .reg .u64 t; cvta.to.shared.u64 t, %1; cvt.u32.u64 %0, t; }"
        : "=r"(a) : "l"(p));
    return a;
}
__device__ __forceinline__ void cpa16(uint32_t dst, const void* src) {
    asm volatile("cp.async.cg.shared.global [%0], [%1], 16;"
                 :: "r"(dst), "l"(src) : "memory");
}
#define CP_COMMIT() asm volatile("cp.async.commit_group;" ::: "memory")
#define CP_WAIT0()  asm volatile("cp.async.wait_group 0;" ::: "memory")
#define CP_WAIT1()  asm volatile("cp.async.wait_group 1;" ::: "memory")

__device__ __forceinline__ void ldsm4(uint32_t addr, uint32_t* r) {
    asm volatile("ldmatrix.sync.aligned.m8n8.x4.shared.b16 {%0,%1,%2,%3}, [%4];"
                 : "=r"(r[0]), "=r"(r[1]), "=r"(r[2]), "=r"(r[3]) : "r"(addr));
}
__device__ __forceinline__ void mma16816(float* c, const uint32_t* a, const uint32_t* b) {
    asm volatile(
        "mma.sync.aligned.m16n8k16.row.col.f32.f16.f16.f32 "
        "{%0,%1,%2,%3}, {%4,%5,%6,%7}, {%8,%9}, {%0,%1,%2,%3};"
        : "+f"(c[0]), "+f"(c[1]), "+f"(c[2]), "+f"(c[3])
        : "r"(a[0]), "r"(a[1]), "r"(a[2]), "r"(a[3]), "r"(b[0]), "r"(b[1]));
}

// ---------------- kNN stage 1: per-half top-3 (2 queries/thread) --------------
__global__ __launch_bounds__(256) void knn_kernel(
    const float* __restrict__ xyz1, const float* __restrict__ xyz2)
{
    __shared__ float4 sp[S_ / 2];
    const int b    = blockIdx.z;
    const int half = blockIdx.y;
    const int t    = threadIdx.x;
    const int sbase = half * (S_ / 2);
    for (int s = t; s < S_ / 2; s += 256) {
        const float* p = xyz2 + ((size_t)b * S_ + sbase + s) * 3;
        sp[s] = make_float4(p[0], p[1], p[2], 0.0f);
    }
    __syncthreads();

    const int nb = blockIdx.x * 512 + t;
    float qx[2], qy[2], qz[2];
    float d0[2], d1[2], d2[2];
    int   i0[2], i1[2], i2[2];
    #pragma unroll
    for (int j = 0; j < 2; j++) {
        const float* q = xyz1 + ((size_t)b * N_ + nb + j * 256) * 3;
        qx[j] = q[0]; qy[j] = q[1]; qz[j] = q[2];
        d0[j] = 3.4e38f; d1[j] = 3.4e38f; d2[j] = 3.4e38f;
        i0[j] = 0; i1[j] = 0; i2[j] = 0;
    }
    #pragma unroll 4
    for (int s = 0; s < S_ / 2; s++) {
        float4 p = sp[s];
        #pragma unroll
        for (int j = 0; j < 2; j++) {
            float dx = qx[j] - p.x, dy = qy[j] - p.y, dz = qz[j] - p.z;
            float d = fmaf(dz, dz, fmaf(dy, dy, dx * dx));
            if (d < d2[j]) {
                if (d < d1[j]) {
                    d2[j] = d1[j]; i2[j] = i1[j];
                    if (d < d0[j]) { d1[j] = d0[j]; i1[j] = i0[j]; d0[j] = d; i0[j] = s; }
                    else           { d1[j] = d;  i1[j] = s; }
                } else { d2[j] = d; i2[j] = s; }
            }
        }
    }
    #pragma unroll
    for (int j = 0; j < 2; j++) {
        size_t base = (((size_t)b * N_ + nb + j * 256) * 2 + half) * 3;
        g_kd[base] = d0[j]; g_kd[base + 1] = d1[j]; g_kd[base + 2] = d2[j];
        g_ki[base] = i0[j] + sbase;
        g_ki[base + 1] = i1[j] + sbase;
        g_ki[base + 2] = i2[j] + sbase;
    }
}

// ---------------- kNN stage 2: merge two sorted triples + weights -------------
__global__ __launch_bounds__(256) void knn_merge_kernel()
{
    const size_t pt = (size_t)blockIdx.x * 256 + threadIdx.x;  // over B*N
    float da[3], db[3]; int ia[3], ib[3];
    #pragma unroll
    for (int k = 0; k < 3; k++) {
        da[k] = g_kd[pt * 6 + k];     ia[k] = g_ki[pt * 6 + k];
        db[k] = g_kd[pt * 6 + 3 + k]; ib[k] = g_ki[pt * 6 + 3 + k];
    }
    float dm[3]; int im[3];
    int i = 0, j = 0;
    #pragma unroll
    for (int k = 0; k < 3; k++) {
        bool takeA = (j >= 3) || (i < 3 && da[i] <= db[j]);
        dm[k] = takeA ? da[i] : db[j];
        im[k] = takeA ? ia[i] : ib[j];
        if (takeA) i++; else j++;
    }
    float a = fmaxf(dm[0], 1e-10f), bb = fmaxf(dm[1], 1e-10f), c = fmaxf(dm[2], 1e-10f);
    float w0 = 1.0f / a, w1 = 1.0f / bb, w2 = 1.0f / c;
    float sw = w0 + w1 + w2;
    g_idx[pt * 3] = im[0]; g_idx[pt * 3 + 1] = im[1]; g_idx[pt * 3 + 2] = im[2];
    g_w[pt * 3] = w0 / sw; g_w[pt * 3 + 1] = w1 / sw; g_w[pt * 3 + 2] = w2 / sw;
}

// ---------------- transpose points2 [B][C][S] -> [B][S][C] --------------------
__global__ void transpose_p2_kernel(const float* __restrict__ p2)
{
    __shared__ float tile[32][33];
    const int b  = blockIdx.z;
    const int s0 = blockIdx.x * 32;
    const int c0 = blockIdx.y * 32;
    #pragma unroll
    for (int r = 0; r < 4; r++) {
        int c = c0 + threadIdx.y + r * 8;
        tile[threadIdx.y + r * 8][threadIdx.x] =
            p2[((size_t)b * C2_ + c) * S_ + s0 + threadIdx.x];
    }
    __syncthreads();
    #pragma unroll
    for (int r = 0; r < 4; r++) {
        int s = s0 + threadIdx.y + r * 8;
        g_p2t[((size_t)b * S_ + s) * C2_ + c0 + threadIdx.x] =
            tile[threadIdx.x][threadIdx.y + r * 8];
    }
}

// ---------------- gather + weighted sum -> xcat channels [0,256) --------------
// 256 thr = 128 channel-pairs x 2 n-points; float2 reads, half2 writes.
__global__ __launch_bounds__(256) void gather_kernel()
{
    const int b  = blockIdx.y;
    const int n0 = blockIdx.x * 32;
    const int cp = threadIdx.x & 127;    // channel pair
    const int no = threadIdx.x >> 7;     // n offset 0/1
    #pragma unroll 2
    for (int it = 0; it < 16; it++) {
        int nl = it * 2 + no;
        size_t base = ((size_t)b * N_ + n0 + nl) * 3;
        int i0 = g_idx[base], i1 = g_idx[base + 1], i2 = g_idx[base + 2];
        float w0 = g_w[base], w1 = g_w[base + 1], w2 = g_w[base + 2];
        const float2* r0 = (const float2*)(g_p2t + ((size_t)b * S_ + i0) * C2_);
        const float2* r1 = (const float2*)(g_p2t + ((size_t)b * S_ + i1) * C2_);
        const float2* r2 = (const float2*)(g_p2t + ((size_t)b * S_ + i2) * C2_);
        float2 a0 = r0[cp], a1 = r1[cp], a2 = r2[cp];
        float v0 = fmaf(w2, a2.x, fmaf(w1, a1.x, w0 * a0.x));
        float v1 = fmaf(w2, a2.y, fmaf(w1, a1.y, w0 * a0.y));
        *(__half2*)(g_xq + ((size_t)b * N_ + n0 + nl) * K1_ + cp * 2) =
            __floats2half2_rn(v0, v1);
    }
}

// ---------------- points1 transpose -> xcat channels [256,384) ----------------
// Tile 32 n x 64 c; coalesced fp32 loads, half2 writes (128B warp sectors).
__global__ void p1t_kernel(const float* __restrict__ p1)
{
    __shared__ float tile[32][66];     // [n][c], pad 66 for aligned float2 reads
    const int b  = blockIdx.z;
    const int n0 = blockIdx.x * 32;
    const int c0 = blockIdx.y * 64;
    const int tx = threadIdx.x;        // 0..31 (n within tile on load)
    const int ty = threadIdx.y;        // 0..7
    #pragma unroll
    for (int r = 0; r < 8; r++) {
        int cc = ty + r * 8;           // 0..63
        tile[tx][cc] = p1[((size_t)b * C1_ + c0 + cc) * N_ + n0 + tx];
    }
    __syncthreads();
    #pragma unroll
    for (int i = 0; i < 4; i++) {
        int nl = ty + i * 8;
        float2 v = *(const float2*)&tile[nl][tx * 2];
        *(__half2*)(g_xq + ((size_t)b * N_ + n0 + nl) * K1_ + 256 + c0 + tx * 2) =
            __floats2half2_rn(v.x, v.y);
    }
}

// ---------------- weight fp16 convert -----------------------------------------
__global__ void wconv_kernel(const float* __restrict__ w,
                             __half* __restrict__ q, int n)
{
    int i = blockIdx.x * 256 + threadIdx.x;
    if (i < n) q[i] = __float2half_rn(w[i]);
}

// ---------------- mma.sync fp16 GEMM (CTA tile 128x128, 2 CTAs/SM) ------------
// FUSE=0: D = W @ X             (layer 1; X = g_xq)
// FUSE=1: D = W @ relu(sc*X+bs) (layer 2; X = y1; affine in fp32 on B frags)
// CTA: 256 thr = 8 warps (2 in M x 4 in N). Warp tile 64x32.
// Epilogue: BN partials from fp32 accs; y stored fp16 via smem-staged flush.
template<int KDIM, bool FUSE>
__global__ __launch_bounds__(256, 2) void gemm_mma(
    const __half* __restrict__ Aq, const __half* __restrict__ Bq,
    const float* __restrict__ bias, __half* __restrict__ Y,
    float* __restrict__ psum, float* __restrict__ pssq,
    const float* __restrict__ sbn)
{
    constexpr int NS = KDIM / 32;                 // K stages of 32
    constexpr uint32_t PITCH  = 80;               // 64B data + 16B pad
    constexpr uint32_t OFF_B  = 128u * PITCH;     // 10240
    constexpr uint32_t STAGE  = OFF_B + 128u * PITCH;  // 20480

    extern __shared__ char sdyn[];
    __shared__ float sm_s[4][128], sm_q[4][128];
    __shared__ float2 sscf[128], sbbf[128];       // fp32 per-channel-pair scale/bias

    const int tid  = threadIdx.x;
    const int lane = tid & 31, wid = tid >> 5;
    const int mw   = wid & 1;        // M block of 64
    const int nw   = wid >> 1;       // N block of 32
    const int b    = blockIdx.z;
    const int mt0  = blockIdx.y * 128;
    const int n0   = blockIdx.x * 128;
    const size_t bn0 = (size_t)b * N_ + n0;
    const uint32_t sb0 = smem_u32(sdyn);

    if (FUSE && tid < 128) {
        sscf[tid] = make_float2(sbn[2 * tid], sbn[2 * tid + 1]);
        sbbf[tid] = make_float2(sbn[256 + 2 * tid], sbn[256 + 2 * tid + 1]);
    }

    auto load_stage = [&](int kt, int buf) {
        uint32_t base = sb0 + (uint32_t)buf * STAGE;
        #pragma unroll
        for (int i = 0; i < 2; i++) {              // A: 128 rows x 4 chunks
            int c = tid + i * 256;
            int row = (c >> 2) & 127, ch = c & 3;
            const __half* src = Aq + (size_t)(mt0 + row) * KDIM + kt + ch * 8;
            cpa16(base + (uint32_t)row * PITCH + ch * 16, src);
        }
        #pragma unroll
        for (int i = 0; i < 2; i++) {              // B: 128 rows x 4 chunks
            int c = tid + i * 256;
            int row = (c >> 2) & 127, ch = c & 3;
            const __half* src = Bq + (bn0 + row) * KDIM + kt + ch * 8;
            cpa16(base + OFF_B + (uint32_t)row * PITCH + ch * 16, src);
        }
        CP_COMMIT();
    };

    float acc[4][4][4] = {};

    load_stage(0, 0);

    #pragma unroll 1
    for (int s = 0; s < NS; s++) {
        if (s + 1 < NS) { load_stage((s + 1) * 32, (s + 1) & 1); CP_WAIT1(); }
        else            { CP_WAIT0(); }
        __syncthreads();

        uint32_t base = sb0 + (uint32_t)(s & 1) * STAGE;
        #pragma unroll
        for (int ks = 0; ks < 2; ks++) {
            uint32_t a[4][4];
            #pragma unroll
            for (int mt = 0; mt < 4; mt++) {
                uint32_t row = (uint32_t)(mw * 64 + mt * 16 + (lane & 15));
                ldsm4(base + row * PITCH + ks * 32 + ((lane >> 4) << 4), a[mt]);
            }
            // fp32 per-k scale/bias for this thread's B fragment positions
            float2 scA, scB, bsA, bsB;
            if (FUSE) {
                int kp = s * 16 + ks * 8 + (lane & 3);
                scA = sscf[kp];     bsA = sbbf[kp];
                scB = sscf[kp + 4]; bsB = sbbf[kp + 4];
            }
            #pragma unroll
            for (int pair = 0; pair < 2; pair++) {
                uint32_t rowB = (uint32_t)(nw * 32 + pair * 16
                               + ((lane >> 4) << 3) + (lane & 7));
                uint32_t bfr[4];
                ldsm4(base + OFF_B + rowB * PITCH
                      + ks * 32 + (((lane >> 3) & 1) << 4), bfr);
                if (FUSE) {
                    #pragma unroll
                    for (int j = 0; j < 4; j++) {
                        const float2 sc = (j & 1) ? scB : scA;
                        const float2 bs = (j & 1) ? bsB : bsA;
                        float2 v = __half22float2(*(__half2*)&bfr[j]);
                        v.x = fmaxf(fmaf(v.x, sc.x, bs.x), 0.0f);
                        v.y = fmaxf(fmaf(v.y, sc.y, bs.y), 0.0f);
                        *(__half2*)&bfr[j] = __floats2half2_rn(v.x, v.y);
                    }
                }
                #pragma unroll
                for (int h = 0; h < 2; h++) {
                    int nt = pair * 2 + h;
                    #pragma unroll
                    for (int mt = 0; mt < 4; mt++)
                        mma16816(acc[mt][nt], a[mt], &bfr[h * 2]);
                }
            }
        }
        __syncthreads();
    }

    // ---- epilogue: bias, BN partials, smem-staged fp16 coalesced flush -------
    float* sy = (float*)sdyn;             // [64][132] per N-half
    const int r = lane >> 2;
    float csum[8] = {}, cssq[8] = {};

    #pragma unroll
    for (int half = 0; half < 2; half++) {
        if ((nw >> 1) == half) {
            #pragma unroll
            for (int mt = 0; mt < 4; mt++) {
                const int m0 = mw * 64 + mt * 16 + r;
                const int m1 = m0 + 8;
                const float bv0 = bias[mt0 + m0], bv1 = bias[mt0 + m1];
                #pragma unroll
                for (int nt = 0; nt < 4; nt++) {
                    float* c = acc[mt][nt];
                    int nl = (nw & 1) * 32 + nt * 8 + (lane & 3) * 2;
                    float v0 = c[0] + bv0, v1 = c[1] + bv0;
                    float v2 = c[2] + bv1, v3 = c[3] + bv1;
                    sy[nl * 132 + m0]       = v0;
                    sy[(nl + 1) * 132 + m0] = v1;
                    sy[nl * 132 + m1]       = v2;
                    sy[(nl + 1) * 132 + m1] = v3;
                    csum[mt * 2]     += v0 + v1;
                    cssq[mt * 2]     += fmaf(v0, v0, v1 * v1);
                    csum[mt * 2 + 1] += v2 + v3;
                    cssq[mt * 2 + 1] += fmaf(v2, v2, v3 * v3);
                }
            }
        }
        __syncthreads();
        // coalesced fp16 flush: 64 rows x 256B, four rows per iteration
        #pragma unroll 4
        for (int i = 0; i < 16; i++) {
            int row = i * 4 + (tid >> 6);
            int c2  = tid & 63;
            __half2 hp = __floats2half2_rn(sy[row * 132 + c2 * 2],
                                           sy[row * 132 + c2 * 2 + 1]);
            *(__half2*)(Y + (bn0 + half * 64 + row) * 256 + mt0 + c2 * 2) = hp;
        }
        __syncthreads();
    }

    // BN partials
    #pragma unroll
    for (int j = 0; j < 8; j++) {
        csum[j] += __shfl_xor_sync(0xffffffffu, csum[j], 1);
        csum[j] += __shfl_xor_sync(0xffffffffu, csum[j], 2);
        cssq[j] += __shfl_xor_sync(0xffffffffu, cssq[j], 1);
        cssq[j] += __shfl_xor_sync(0xffffffffu, cssq[j], 2);
    }
    if ((lane & 3) == 0) {
        #pragma unroll
        for (int mt = 0; mt < 4; mt++) {
            #pragma unroll
            for (int h = 0; h < 2; h++) {
                int ch = mw * 64 + mt * 16 + r + h * 8;
                sm_s[nw][ch] = csum[mt * 2 + h];
                sm_q[nw][ch] = cssq[mt * 2 + h];
            }
        }
    }
    __syncthreads();
    if (tid < 128) {
        int cta = blockIdx.x + blockIdx.z * gridDim.x;
        psum[(mt0 + tid) * 1024 + cta] =
            sm_s[0][tid] + sm_s[1][tid] + sm_s[2][tid] + sm_s[3][tid];
        pssq[(mt0 + tid) * 1024 + cta] =
            sm_q[0][tid] + sm_q[1][tid] + sm_q[2][tid] + sm_q[3][tid];
    }
}

// ---------------- BN fold: reduce 1024 partials per channel -------------------
__global__ __launch_bounds__(256) void stats2_kernel(
    const float* __restrict__ g, const float* __restrict__ beta,
    float* __restrict__ sb)
{
    const int o = blockIdx.x;
    const int t = threadIdx.x;
    float s = 0.0f, ss = 0.0f;
    #pragma unroll
    for (int i = 0; i < 4; i++) {
        s  += g_psum[o * 1024 + t * 4 + i];
        ss += g_pssq[o * 1024 + t * 4 + i];
    }
    const int lane = t & 31, w = t >> 5;
    #pragma unroll
    for (int off = 16; off; off >>= 1) {
        s  += __shfl_down_sync(0xffffffffu, s,  off);
        ss += __shfl_down_sync(0xffffffffu, ss, off);
    }
    __shared__ float rs[8], rss[8];
    if (lane == 0) { rs[w] = s; rss[w] = ss; }
    __syncthreads();
    if (t == 0) {
        float ts = 0.0f, tss = 0.0f;
        #pragma unroll
        for (int i = 0; i < 8; i++) { ts += rs[i]; tss += rss[i]; }
        float mean = ts * CNT_INV;
        float var  = tss * CNT_INV - mean * mean;
        float rstd = rsqrtf(var + BN_EPS);
        float sc = g[o] * rstd;
        sb[o]       = sc;
        sb[256 + o] = beta[o] - mean * sc;
    }
}

// ---------------- final norm + relu + transpose -> out [B][256][N] ------------
// Tile: 32 n-rows x 64 m. half2 loads (128B rows), fp32 writes (128B rows).
__global__ __launch_bounds__(256) void outt_kernel(
    const __half* __restrict__ y, const float* __restrict__ sb,
    float* __restrict__ out)
{
    __shared__ float tile[32][65];
    const int b  = blockIdx.z;
    const int n0 = blockIdx.x * 32;
    const int m0 = blockIdx.y * 64;
    const int tx = threadIdx.x;      // 0..31
    const int ty = threadIdx.y;      // 0..7
    #pragma unroll
    for (int r = 0; r < 4; r++) {
        int n = n0 + ty + r * 8;
        __half2 hv = *(const __half2*)(y + ((size_t)b * N_ + n) * 256 + m0 + tx * 2);
        float2 f = __half22float2(hv);
        tile[ty + r * 8][tx * 2]     = f.x;
        tile[ty + r * 8][tx * 2 + 1] = f.y;
    }
    __syncthreads();
    #pragma unroll
    for (int r = 0; r < 8; r++) {
        int m = m0 + ty + r * 8;
        float sc = sb[m], bs = sb[256 + m];
        out[((size_t)b * 256 + m) * N_ + n0 + tx] =
            fmaxf(fmaf(tile[tx][ty + r * 8], sc, bs), 0.0f);
    }
}

// ---------------- launcher ----------------------------------------------------
extern "C" void kernel_launch(void* const* d_in, const int* in_sizes, int n_in,
                              void* d_out, int out_size)
{
    const float* xyz1 = (const float*)d_in[0];
    const float* xyz2 = (const float*)d_in[1];
    const float* pts1 = (const float*)d_in[2];
    const float* pts2 = (const float*)d_in[3];
    const float* W0   = (const float*)d_in[4];
    const float* b0   = (const float*)d_in[5];
    const float* gg0  = (const float*)d_in[6];
    const float* be0  = (const float*)d_in[7];
    const float* W1   = (const float*)d_in[8];
    const float* b1   = (const float*)d_in[9];
    const float* gg1  = (const float*)d_in[10];
    const float* be1  = (const float*)d_in[11];
    float* out = (float*)d_out;

    __half *xq, *w0q, *w1q, *y, *y2;
    float *psum, *pssq, *sb1, *sb2;
    cudaGetSymbolAddress((void**)&xq,  g_xq);
    cudaGetSymbolAddress((void**)&w0q, g_w0q);
    cudaGetSymbolAddress((void**)&w1q, g_w1q);
    cudaGetSymbolAddress((void**)&y,   g_y);
    cudaGetSymbolAddress((void**)&y2,  g_y2);
    cudaGetSymbolAddress((void**)&psum, g_psum);
    cudaGetSymbolAddress((void**)&pssq, g_pssq);
    cudaGetSymbolAddress((void**)&sb1, g_sb1);
    cudaGetSymbolAddress((void**)&sb2, g_sb2);

    const int GEMM_SMEM = 40960;   // max(2 stages 40960, sy 64*132*4=33792)
    cudaFuncSetAttribute(gemm_mma<K1_, false>, cudaFuncAttributeMaxDynamicSharedMemorySize, GEMM_SMEM);
    cudaFuncSetAttribute(gemm_mma<O_,  true >, cudaFuncAttributeMaxDynamicSharedMemorySize, GEMM_SMEM);

    // prep
    wconv_kernel<<<(O_ * K1_ + 255) / 256, 256>>>(W0, w0q, O_ * K1_);
    wconv_kernel<<<(O_ * O_  + 255) / 256, 256>>>(W1, w1q, O_ * O_);
    knn_kernel<<<dim3(N_ / 512, 2, B_), 256>>>(xyz1, xyz2);
    knn_merge_kernel<<<(int)((size_t)B_ * N_ / 256), 256>>>();
    transpose_p2_kernel<<<dim3(S_ / 32, C2_ / 32, B_), dim3(32, 8)>>>(pts2);
    gather_kernel<<<dim3(N_ / 32, B_), 256>>>();
    p1t_kernel<<<dim3(N_ / 32, C1_ / 64, B_), dim3(32, 8)>>>(pts1);

    // layer 1 -> y1
    gemm_mma<K1_, false><<<dim3(N_ / 128, 2, B_), 256, GEMM_SMEM>>>(
        w0q, xq, b0, y, psum, pssq, nullptr);
    stats2_kernel<<<256, 256>>>(gg0, be0, sb1);

    // layer 2: reads y1, fp32 norm+relu on B fragments, writes y2
    gemm_mma<O_, true><<<dim3(N_ / 128, 2, B_), 256, GEMM_SMEM>>>(
        w1q, y, b1, y2, psum, pssq, sb1);
    stats2_kernel<<<256, 256>>>(gg1, be1, sb2);

    // output
    outt_kernel<<<dim3(N_ / 32, 4, B_), dim3(32, 8)>>>(y2, sb2, out);
}